// round 6
// baseline (speedup 1.0000x reference)
#include <cuda_runtime.h>
#include <math.h>

#define B_SZ 8
#define C_SZ 256
#define H_SZ 96
#define W_SZ 96
#define HW   (H_SZ * W_SZ)   // 9216

typedef unsigned long long ull;

// ---------------- packed f32x2 helpers (FFMA2 path) ----------------
__device__ __forceinline__ ull pack2(float x, float y) {
    ull r;
    asm("mov.b64 %0, {%1, %2};" : "=l"(r) : "f"(x), "f"(y));
    return r;
}
__device__ __forceinline__ void unpack2(ull v, float& x, float& y) {
    asm("mov.b64 {%0, %1}, %2;" : "=f"(x), "=f"(y) : "l"(v));
}
__device__ __forceinline__ void ffma2(ull& d, ull a, ull b) {
    asm("fma.rn.f32x2 %0, %1, %2, %3;" : "=l"(d) : "l"(a), "l"(b), "l"(d));
}

// ---------------- scratch ----------------
__device__ float g_yu[B_SZ * HW];
__device__ float g_Aq[C_SZ], g_Bq[C_SZ], g_Ak[C_SZ], g_Bk[C_SZ];
__device__ float g_q[(size_t)B_SZ * H_SZ * C_SZ * W_SZ];  // [B][H][C][W]
__device__ float g_k[(size_t)B_SZ * H_SZ * C_SZ * W_SZ];
__device__ float g_v[(size_t)B_SZ * H_SZ * C_SZ * W_SZ];

// ---------------- kernel 0: fold y-branch weights ----------------
__global__ void prep_kernel(const float* __restrict__ wy, const float* __restrict__ by,
                            const float* __restrict__ wq, const float* __restrict__ bq,
                            const float* __restrict__ wk, const float* __restrict__ bk)
{
    int c = threadIdx.x;
    const float* wqr = wq + c * C_SZ;
    const float* wkr = wk + c * C_SZ;
    float aq = 0.f, bqs = 0.f, ak = 0.f, bks = 0.f;
    for (int j = 0; j < C_SZ; j++) {
        float wyj = wy[j], byj = by[j];
        aq += wqr[j] * wyj;  bqs += wqr[j] * byj;
        ak += wkr[j] * wyj;  bks += wkr[j] * byj;
    }
    g_Aq[c] = aq;  g_Bq[c] = bqs + bq[c];
    g_Ak[c] = ak;  g_Bk[c] = bks + bk[c];
}

// ---------------- kernel 1: bilinear 24x24 -> 96x96 ----------------
__global__ void upsample_kernel(const float* __restrict__ y)
{
    int idx = blockIdx.x * blockDim.x + threadIdx.x;
    if (idx >= B_SZ * HW) return;
    int b  = idx / HW;
    int r  = idx - b * HW;
    int oh = r / W_SZ;
    int ow = r - oh * W_SZ;
    float sy = (oh + 0.5f) * 0.25f - 0.5f;
    float sx = (ow + 0.5f) * 0.25f - 0.5f;
    int y0 = (int)floorf(sy);  float fy = sy - (float)y0;
    int x0 = (int)floorf(sx);  float fx = sx - (float)x0;
    int y0c = max(0, min(23, y0)),     y1c = max(0, min(23, y0 + 1));
    int x0c = max(0, min(23, x0)),     x1c = max(0, min(23, x0 + 1));
    const float* yb = y + b * 576;
    float v00 = yb[y0c * 24 + x0c], v01 = yb[y0c * 24 + x1c];
    float v10 = yb[y1c * 24 + x0c], v11 = yb[y1c * 24 + x1c];
    g_yu[idx] = (1.f - fy) * ((1.f - fx) * v00 + fx * v01)
              +        fy  * ((1.f - fx) * v10 + fx * v11);
}

// ---------------- kernel 2: fused QKV conv as SGEMM (FFMA2, dup-A) ----------------
__global__ __launch_bounds__(256, 2) void conv_gemm_kernel(
    const float* __restrict__ x,
    const float* __restrict__ wq, const float* __restrict__ bq,
    const float* __restrict__ wk, const float* __restrict__ bk,
    const float* __restrict__ wv, const float* __restrict__ bv)
{
    __shared__ __align__(16) float As[2][16][256];   // A tile, k-major, DUPLICATED pairs
    __shared__ __align__(16) float Bs[2][16][128];

    int b  = blockIdx.z;
    int n0 = blockIdx.x * 128;
    int m0 = blockIdx.y * 128;
    int sel = m0 >> 8;                          // 0=q, 1=k, 2=v
    const float* W    = (sel == 0) ? wq : (sel == 1) ? wk : wv;
    const float* bias = (sel == 0) ? bq : (sel == 1) ? bk : bv;
    int mrow0 = m0 & 255;
    const float* Xb = x + (size_t)b * C_SZ * HW;

    int tid = threadIdx.x;
    int a_k = (tid & 3) * 4;
    int a_m = tid >> 2;          // 0..63
    int b_n = (tid & 31) * 4;
    int b_k = tid >> 5;          // 0..7
    int tx  = tid & 15, ty = tid >> 4;

    ull acc2[8][4];
    #pragma unroll
    for (int i = 0; i < 8; i++)
        #pragma unroll
        for (int j = 0; j < 4; j++) acc2[i][j] = 0ULL;

    auto load_tiles = [&](int k0, int buf) {
        #pragma unroll
        for (int p = 0; p < 2; p++) {
            int m = a_m + p * 64;
            float4 v = *reinterpret_cast<const float4*>(&W[(mrow0 + m) * C_SZ + k0 + a_k]);
            *reinterpret_cast<float2*>(&As[buf][a_k + 0][2 * m]) = make_float2(v.x, v.x);
            *reinterpret_cast<float2*>(&As[buf][a_k + 1][2 * m]) = make_float2(v.y, v.y);
            *reinterpret_cast<float2*>(&As[buf][a_k + 2][2 * m]) = make_float2(v.z, v.z);
            *reinterpret_cast<float2*>(&As[buf][a_k + 3][2 * m]) = make_float2(v.w, v.w);
        }
        #pragma unroll
        for (int p = 0; p < 2; p++) {
            int kk = b_k + p * 8;
            *reinterpret_cast<float4*>(&Bs[buf][kk][b_n]) =
                *reinterpret_cast<const float4*>(&Xb[(size_t)(k0 + kk) * HW + n0 + b_n]);
        }
    };

    load_tiles(0, 0);
    __syncthreads();

    #pragma unroll 1
    for (int kt = 0; kt < 16; kt++) {
        int buf = kt & 1;
        if (kt < 15) load_tiles((kt + 1) * 16, buf ^ 1);
        #pragma unroll
        for (int kk = 0; kk < 16; kk++) {
            longlong2 bl0 = *reinterpret_cast<const longlong2*>(&Bs[buf][kk][tx * 8]);
            longlong2 bl1 = *reinterpret_cast<const longlong2*>(&Bs[buf][kk][tx * 8 + 4]);
            ull bp[4];
            bp[0] = (ull)bl0.x; bp[1] = (ull)bl0.y;
            bp[2] = (ull)bl1.x; bp[3] = (ull)bl1.y;
            ulonglong2 a0 = *reinterpret_cast<const ulonglong2*>(&As[buf][kk][ty * 16]);
            ulonglong2 a1 = *reinterpret_cast<const ulonglong2*>(&As[buf][kk][ty * 16 + 4]);
            ulonglong2 a2 = *reinterpret_cast<const ulonglong2*>(&As[buf][kk][ty * 16 + 8]);
            ulonglong2 a3 = *reinterpret_cast<const ulonglong2*>(&As[buf][kk][ty * 16 + 12]);
            ull aa[8] = {a0.x, a0.y, a1.x, a1.y, a2.x, a2.y, a3.x, a3.y};
            #pragma unroll
            for (int i = 0; i < 8; i++)
                #pragma unroll
                for (int j = 0; j < 4; j++)
                    ffma2(acc2[i][j], aa[i], bp[j]);
        }
        __syncthreads();
    }

    // epilogue: bias, gate (q/k), write transposed [B][H][C][W]
    float* outbuf = (sel == 0) ? g_q : (sel == 1) ? g_k : g_v;
    const float* Agp = (sel == 0) ? g_Aq : g_Ak;
    const float* Bgp = (sel == 0) ? g_Bq : g_Bk;
    const float* yub = g_yu + b * HW;

    float yuv[8];
    if (sel < 2) {
        #pragma unroll
        for (int j = 0; j < 8; j++) yuv[j] = yub[n0 + tx * 8 + j];
    }

    #pragma unroll
    for (int i = 0; i < 8; i++) {
        int c = mrow0 + ty * 8 + i;
        float bi = bias[c];
        float Ag = 0.f, Bg = 0.f;
        if (sel < 2) { Ag = Agp[c]; Bg = Bgp[c]; }
        float row[8];
        #pragma unroll
        for (int j = 0; j < 4; j++) unpack2(acc2[i][j], row[2 * j], row[2 * j + 1]);
        #pragma unroll
        for (int j = 0; j < 8; j++) {
            int n = n0 + tx * 8 + j;
            float val = row[j] + bi;
            if (sel < 2) val *= (yuv[j] * Ag + Bg);
            int h = n / 96;
            int w = n - h * 96;
            outbuf[(((size_t)b * H_SZ + h) * C_SZ + c) * W_SZ + w] = val;
        }
    }
}

// ---------------- kernel 3: channel attention, 512 threads, dup-operand FFMA2 ----------------
// S = Q K^T / sqrt(32)  (256x256, K=96); softmax rows; O = P V (256x96, K=256).
#define KS_STRIDE 258     // K transposed [w][d], even stride -> conflict-free LDS.64 pairs
#define QD_STRIDE 130     // Q transposed DUPLICATED [w][2r], 64 rows -> 128 + pad
#define PS_STRIDE 66      // P transposed [d][r]
#define ATTN_SMEM_FLOATS (96 * KS_STRIDE + 96 * QD_STRIDE + 256 * PS_STRIDE)  // 54144
#define ATTN_SMEM_BYTES  (ATTN_SMEM_FLOATS * 4)                               // 216576

__global__ __launch_bounds__(512, 1) void attn_kernel(float* __restrict__ out)
{
    extern __shared__ __align__(16) float sm[];
    float* Ks = sm;                       // [w][d]   96 x 258
    float* Qd = Ks + 96 * KS_STRIDE;      // [w][2r]  96 x 130 ; reused as dup-V double buffer
    float* Ps = Qd + 96 * QD_STRIDE;      // [d][r]  256 x 66

    int bh = blockIdx.x;
    int b  = bh / H_SZ;
    int h  = bh - b * H_SZ;
    const float* Q = g_q + (size_t)bh * C_SZ * W_SZ;
    const float* K = g_k + (size_t)bh * C_SZ * W_SZ;
    const float* V = g_v + (size_t)bh * C_SZ * W_SZ;

    int tid = threadIdx.x;
    int ty  = tid >> 5;   // warp 0..15
    int tx  = tid & 31;

    // K -> smem transposed
    for (int idx = tid; idx < C_SZ * W_SZ; idx += 512) {
        int d = idx / W_SZ;
        int w = idx - d * W_SZ;
        Ks[w * KS_STRIDE + d] = K[idx];
    }
    __syncthreads();

    const float inv_s = 0.17677669529663687f;  // 1/sqrt(32)

    for (int t = 0; t < 4; t++) {
        int r0 = t * 64;

        // Q tile -> smem transposed + duplicated pairs
        for (int idx = tid; idx < 64 * W_SZ; idx += 512) {
            int r = idx / W_SZ;
            int w = idx - r * W_SZ;
            float q = Q[(r0 + r) * W_SZ + w];
            *reinterpret_cast<float2*>(&Qd[w * QD_STRIDE + 2 * r]) = make_float2(q, q);
        }
        __syncthreads();

        // S = Qt @ K^T: warp -> 4 rows (ty*4..), lane -> 4 col-pairs (2tx+64j)
        ull acc2[4][4];
        #pragma unroll
        for (int i = 0; i < 4; i++)
            #pragma unroll
            for (int j = 0; j < 4; j++) acc2[i][j] = 0ULL;

        const float* qb = Qd + 8 * ty;     // 2*(ty*4)
        const float* kb = Ks + 2 * tx;
        #pragma unroll 2
        for (int w = 0; w < 96; w++) {
            ull bp[4], aa[4];
            #pragma unroll
            for (int j = 0; j < 4; j++)
                bp[j] = *reinterpret_cast<const ull*>(&kb[w * KS_STRIDE + 64 * j]);
            #pragma unroll
            for (int i = 0; i < 4; i++)
                aa[i] = *reinterpret_cast<const ull*>(&qb[w * QD_STRIDE + 2 * i]);
            #pragma unroll
            for (int i = 0; i < 4; i++)
                #pragma unroll
                for (int j = 0; j < 4; j++)
                    ffma2(acc2[i][j], aa[i], bp[j]);
        }

        // softmax per row (row fully inside one warp), store P transposed
        #pragma unroll
        for (int i = 0; i < 4; i++) {
            float p[8];
            #pragma unroll
            for (int j = 0; j < 4; j++) unpack2(acc2[i][j], p[2 * j], p[2 * j + 1]);
            float m = p[0];
            #pragma unroll
            for (int j = 1; j < 8; j++) m = fmaxf(m, p[j]);
            #pragma unroll
            for (int off = 16; off > 0; off >>= 1)
                m = fmaxf(m, __shfl_xor_sync(0xffffffffu, m, off));
            float s = 0.f;
            #pragma unroll
            for (int j = 0; j < 8; j++) {
                float e = __expf((p[j] - m) * inv_s);
                p[j] = e;
                s += e;
            }
            #pragma unroll
            for (int off = 16; off > 0; off >>= 1)
                s += __shfl_xor_sync(0xffffffffu, s, off);
            float rs = 1.f / s;
            int r = ty * 4 + i;
            #pragma unroll
            for (int j = 0; j < 4; j++) {
                Ps[(2 * tx + 64 * j    ) * PS_STRIDE + r] = p[2 * j]     * rs;
                Ps[(2 * tx + 64 * j + 1) * PS_STRIDE + r] = p[2 * j + 1] * rs;
            }
        }
        __syncthreads();   // Ps visible; all Qd reads done (V buffers reuse Qd)

        // O = P @ V: warp -> 2 row-pairs (rows ty*4..+3), lane -> 3 cols (tx+32j)
        // V streamed in 32-row chunks, stored duplicated, double-buffered.
        float* Vb0 = Qd;
        float* Vb1 = Qd + 32 * 192;   // 6144 floats each; region holds 12480

        ull acco2[2][3];
        #pragma unroll
        for (int i = 0; i < 2; i++)
            #pragma unroll
            for (int j = 0; j < 3; j++) acco2[i][j] = 0ULL;

        // preload chunk 0
        #pragma unroll
        for (int u = 0; u < 6; u++) {
            int idx = tid + u * 512;
            int dd = idx / 96, w = idx - dd * 96;
            float v = V[idx];
            *reinterpret_cast<float2*>(&Vb0[dd * 192 + 2 * w]) = make_float2(v, v);
        }
        __syncthreads();

        #pragma unroll 1
        for (int c = 0; c < 8; c++) {
            float vreg[6];
            if (c < 7) {
                #pragma unroll
                for (int u = 0; u < 6; u++)
                    vreg[u] = V[(c + 1) * 3072 + tid + u * 512];
            }
            const float* Vb = (c & 1) ? Vb1 : Vb0;
            const float* pb = Ps + (c * 32) * PS_STRIDE + ty * 4;
            const float* vb = Vb + 2 * tx;
            #pragma unroll 2
            for (int dd = 0; dd < 32; dd++) {
                ull ap[2], bp[3];
                #pragma unroll
                for (int ii = 0; ii < 2; ii++)
                    ap[ii] = *reinterpret_cast<const ull*>(&pb[dd * PS_STRIDE + 2 * ii]);
                #pragma unroll
                for (int j = 0; j < 3; j++)
                    bp[j] = *reinterpret_cast<const ull*>(&vb[dd * 192 + 64 * j]);
                #pragma unroll
                for (int ii = 0; ii < 2; ii++)
                    #pragma unroll
                    for (int j = 0; j < 3; j++)
                        ffma2(acco2[ii][j], ap[ii], bp[j]);
            }
            if (c < 7) {
                float* Vw = (c & 1) ? Vb0 : Vb1;
                #pragma unroll
                for (int u = 0; u < 6; u++) {
                    int idx = tid + u * 512;
                    int dd = idx / 96, w = idx - dd * 96;
                    *reinterpret_cast<float2*>(&Vw[dd * 192 + 2 * w]) =
                        make_float2(vreg[u], vreg[u]);
                }
            }
            __syncthreads();
        }

        // write O back as [B][C][H][W]
        float* ob = out + (size_t)b * C_SZ * HW + (size_t)h * W_SZ + tx;
        #pragma unroll
        for (int ii = 0; ii < 2; ii++) {
            int c = r0 + ty * 4 + 2 * ii;
            #pragma unroll
            for (int j = 0; j < 3; j++) {
                float o0, o1;
                unpack2(acco2[ii][j], o0, o1);
                ob[(size_t)c       * HW + j * 32] = o0;
                ob[(size_t)(c + 1) * HW + j * 32] = o1;
            }
        }
    }
}

// ---------------- launch ----------------
extern "C" void kernel_launch(void* const* d_in, const int* in_sizes, int n_in,
                              void* d_out, int out_size)
{
    const float* x  = (const float*)d_in[0];
    const float* y  = (const float*)d_in[1];
    const float* wy = (const float*)d_in[2];
    const float* by = (const float*)d_in[3];
    const float* wq = (const float*)d_in[4];
    const float* bq = (const float*)d_in[5];
    const float* wk = (const float*)d_in[6];
    const float* bk = (const float*)d_in[7];
    const float* wv = (const float*)d_in[8];
    const float* bv = (const float*)d_in[9];
    float* out = (float*)d_out;

    cudaFuncSetAttribute(attn_kernel, cudaFuncAttributeMaxDynamicSharedMemorySize,
                         ATTN_SMEM_BYTES);

    prep_kernel<<<1, 256>>>(wy, by, wq, bq, wk, bk);
    upsample_kernel<<<(B_SZ * HW + 255) / 256, 256>>>(y);
    dim3 g(HW / 128, 768 / 128, B_SZ);   // (72, 6, 8)
    conv_gemm_kernel<<<g, 256>>>(x, wq, bq, wk, bk, wv, bv);
    attn_kernel<<<B_SZ * H_SZ, 512, ATTN_SMEM_BYTES>>>(out);
}

// round 11
// speedup vs baseline: 1.2138x; 1.2138x over previous
#include <cuda_runtime.h>
#include <math.h>

#define B_SZ 8
#define C_SZ 256
#define H_SZ 96
#define W_SZ 96
#define HW   (H_SZ * W_SZ)   // 9216

typedef unsigned long long ull;

// ---------------- packed f32x2 helpers (FFMA2 path) ----------------
__device__ __forceinline__ ull pack2(float x, float y) {
    ull r;
    asm("mov.b64 %0, {%1, %2};" : "=l"(r) : "f"(x), "f"(y));
    return r;
}
__device__ __forceinline__ void unpack2(ull v, float& x, float& y) {
    asm("mov.b64 {%0, %1}, %2;" : "=f"(x), "=f"(y) : "l"(v));
}
__device__ __forceinline__ void ffma2(ull& d, ull a, ull b) {
    asm("fma.rn.f32x2 %0, %1, %2, %3;" : "=l"(d) : "l"(a), "l"(b), "l"(d));
}

// ---------------- scratch ----------------
__device__ float g_yu[B_SZ * HW];
__device__ float g_Aq[C_SZ], g_Bq[C_SZ], g_Ak[C_SZ], g_Bk[C_SZ];
__device__ float g_q[(size_t)B_SZ * H_SZ * C_SZ * W_SZ];  // [B][H][C][W]
__device__ float g_k[(size_t)B_SZ * H_SZ * C_SZ * W_SZ];
__device__ float g_v[(size_t)B_SZ * H_SZ * C_SZ * W_SZ];

// ---------------- kernel 0: fold y-branch weights ----------------
__global__ void prep_kernel(const float* __restrict__ wy, const float* __restrict__ by,
                            const float* __restrict__ wq, const float* __restrict__ bq,
                            const float* __restrict__ wk, const float* __restrict__ bk)
{
    int c = threadIdx.x;
    const float* wqr = wq + c * C_SZ;
    const float* wkr = wk + c * C_SZ;
    float aq = 0.f, bqs = 0.f, ak = 0.f, bks = 0.f;
    for (int j = 0; j < C_SZ; j++) {
        float wyj = wy[j], byj = by[j];
        aq += wqr[j] * wyj;  bqs += wqr[j] * byj;
        ak += wkr[j] * wyj;  bks += wkr[j] * byj;
    }
    g_Aq[c] = aq;  g_Bq[c] = bqs + bq[c];
    g_Ak[c] = ak;  g_Bk[c] = bks + bk[c];
}

// ---------------- kernel 1: bilinear 24x24 -> 96x96 ----------------
__global__ void upsample_kernel(const float* __restrict__ y)
{
    int idx = blockIdx.x * blockDim.x + threadIdx.x;
    if (idx >= B_SZ * HW) return;
    int b  = idx / HW;
    int r  = idx - b * HW;
    int oh = r / W_SZ;
    int ow = r - oh * W_SZ;
    float sy = (oh + 0.5f) * 0.25f - 0.5f;
    float sx = (ow + 0.5f) * 0.25f - 0.5f;
    int y0 = (int)floorf(sy);  float fy = sy - (float)y0;
    int x0 = (int)floorf(sx);  float fx = sx - (float)x0;
    int y0c = max(0, min(23, y0)),     y1c = max(0, min(23, y0 + 1));
    int x0c = max(0, min(23, x0)),     x1c = max(0, min(23, x0 + 1));
    const float* yb = y + b * 576;
    float v00 = yb[y0c * 24 + x0c], v01 = yb[y0c * 24 + x1c];
    float v10 = yb[y1c * 24 + x0c], v11 = yb[y1c * 24 + x1c];
    g_yu[idx] = (1.f - fy) * ((1.f - fx) * v00 + fx * v01)
              +        fy  * ((1.f - fx) * v10 + fx * v11);
}

// ---------------- kernel 2: fused QKV conv as SGEMM (FFMA2, pack-in-loop) ----------------
__global__ __launch_bounds__(256, 2) void conv_gemm_kernel(
    const float* __restrict__ x,
    const float* __restrict__ wq, const float* __restrict__ bq,
    const float* __restrict__ wk, const float* __restrict__ bk,
    const float* __restrict__ wv, const float* __restrict__ bv)
{
    __shared__ __align__(16) float As[2][16][132];   // A tile transposed (k-major), padded
    __shared__ __align__(16) float Bs[2][16][128];

    int b  = blockIdx.z;
    int n0 = blockIdx.x * 128;
    int m0 = blockIdx.y * 128;
    int sel = m0 >> 8;                          // 0=q, 1=k, 2=v
    const float* W    = (sel == 0) ? wq : (sel == 1) ? wk : wv;
    const float* bias = (sel == 0) ? bq : (sel == 1) ? bk : bv;
    int mrow0 = m0 & 255;
    const float* Xb = x + (size_t)b * C_SZ * HW;

    int tid = threadIdx.x;
    int a_k = (tid & 3) * 4;
    int a_m = tid >> 2;          // 0..63
    int b_n = (tid & 31) * 4;
    int b_k = tid >> 5;          // 0..7
    int tx  = tid & 15, ty = tid >> 4;

    ull acc2[8][4];
    #pragma unroll
    for (int i = 0; i < 8; i++)
        #pragma unroll
        for (int j = 0; j < 4; j++) acc2[i][j] = 0ULL;

    auto load_tiles = [&](int k0, int buf) {
        #pragma unroll
        for (int p = 0; p < 2; p++) {
            int m = a_m + p * 64;
            float4 v = *reinterpret_cast<const float4*>(&W[(mrow0 + m) * C_SZ + k0 + a_k]);
            As[buf][a_k + 0][m] = v.x;
            As[buf][a_k + 1][m] = v.y;
            As[buf][a_k + 2][m] = v.z;
            As[buf][a_k + 3][m] = v.w;
        }
        #pragma unroll
        for (int p = 0; p < 2; p++) {
            int kk = b_k + p * 8;
            *reinterpret_cast<float4*>(&Bs[buf][kk][b_n]) =
                *reinterpret_cast<const float4*>(&Xb[(size_t)(k0 + kk) * HW + n0 + b_n]);
        }
    };

    load_tiles(0, 0);
    __syncthreads();

    #pragma unroll 1
    for (int kt = 0; kt < 16; kt++) {
        int buf = kt & 1;
        if (kt < 15) load_tiles((kt + 1) * 16, buf ^ 1);
        #pragma unroll
        for (int kk = 0; kk < 16; kk++) {
            longlong2 bl0 = *reinterpret_cast<const longlong2*>(&Bs[buf][kk][tx * 8]);
            longlong2 bl1 = *reinterpret_cast<const longlong2*>(&Bs[buf][kk][tx * 8 + 4]);
            ull bp[4];
            bp[0] = (ull)bl0.x; bp[1] = (ull)bl0.y;
            bp[2] = (ull)bl1.x; bp[3] = (ull)bl1.y;
            float4 a0 = *reinterpret_cast<const float4*>(&As[buf][kk][ty * 8]);
            float4 a1 = *reinterpret_cast<const float4*>(&As[buf][kk][ty * 8 + 4]);
            float av[8] = {a0.x, a0.y, a0.z, a0.w, a1.x, a1.y, a1.z, a1.w};
            #pragma unroll
            for (int i = 0; i < 8; i++) {
                ull aa = pack2(av[i], av[i]);
                #pragma unroll
                for (int j = 0; j < 4; j++)
                    ffma2(acc2[i][j], aa, bp[j]);
            }
        }
        __syncthreads();
    }

    float* outbuf = (sel == 0) ? g_q : (sel == 1) ? g_k : g_v;
    const float* Agp = (sel == 0) ? g_Aq : g_Ak;
    const float* Bgp = (sel == 0) ? g_Bq : g_Bk;
    const float* yub = g_yu + b * HW;

    float yuv[8];
    if (sel < 2) {
        #pragma unroll
        for (int j = 0; j < 8; j++) yuv[j] = yub[n0 + tx * 8 + j];
    }

    #pragma unroll
    for (int i = 0; i < 8; i++) {
        int c = mrow0 + ty * 8 + i;
        float bi = bias[c];
        float Ag = 0.f, Bg = 0.f;
        if (sel < 2) { Ag = Agp[c]; Bg = Bgp[c]; }
        float row[8];
        #pragma unroll
        for (int j = 0; j < 4; j++) unpack2(acc2[i][j], row[2 * j], row[2 * j + 1]);
        #pragma unroll
        for (int j = 0; j < 8; j++) {
            int n = n0 + tx * 8 + j;
            float val = row[j] + bi;
            if (sel < 2) val *= (yuv[j] * Ag + Bg);
            int h = n / 96;
            int w = n - h * 96;
            outbuf[(((size_t)b * H_SZ + h) * C_SZ + c) * W_SZ + w] = val;
        }
    }
}

// ---------------- kernel 3: channel attention, 512 threads, 128-row S tiles ----------------
// S = Q K^T / sqrt(32)  (256x256, K=96); softmax rows; O = P V (256x96, K=256).
#define KS_STRIDE 258     // K transposed [w][d]
#define QS_STRIDE 98      // Q natural [r][w], 128 rows
#define PS_STRIDE 66      // P transposed [d][r], 64 rows per half
#define ATTN_SMEM_FLOATS (96 * KS_STRIDE + 128 * QS_STRIDE + 256 * PS_STRIDE)  // 54208
#define ATTN_SMEM_BYTES  (ATTN_SMEM_FLOATS * 4)                                // 216832

__global__ __launch_bounds__(512, 1) void attn_kernel(float* __restrict__ out)
{
    extern __shared__ __align__(16) float sm[];
    float* Ks = sm;                       // [w][d]   96 x 258
    float* Qs = Ks + 96 * KS_STRIDE;      // [r][w]  128 x 98 ; reused as V double buffer
    float* Ps = Qs + 128 * QS_STRIDE;     // [d][r]  256 x 66 (64 rows per half)

    int bh = blockIdx.x;
    int b  = bh / H_SZ;
    int h  = bh - b * H_SZ;
    const float* Q = g_q + (size_t)bh * C_SZ * W_SZ;
    const float* K = g_k + (size_t)bh * C_SZ * W_SZ;
    const float* V = g_v + (size_t)bh * C_SZ * W_SZ;

    int tid = threadIdx.x;
    int ty  = tid >> 5;   // warp 0..15
    int tx  = tid & 31;

    // K -> smem transposed
    for (int idx = tid; idx < C_SZ * W_SZ; idx += 512) {
        int d = idx / W_SZ;
        int w = idx - d * W_SZ;
        Ks[w * KS_STRIDE + d] = K[idx];
    }
    __syncthreads();

    const float inv_s = 0.17677669529663687f;  // 1/sqrt(32)

    #pragma unroll 1
    for (int t = 0; t < 2; t++) {
        int r0 = t * 128;

        // Q tile (128 rows) -> smem natural [r][w]
        for (int idx = tid; idx < 128 * W_SZ; idx += 512) {
            int r = idx / W_SZ;
            int w = idx - r * W_SZ;
            Qs[r * QS_STRIDE + w] = Q[(r0 + r) * W_SZ + w];
        }
        __syncthreads();

        // S = Q @ K^T: warp -> 8 rows (ty*8..), lane -> 4 col-pairs (2tx+64j)
        ull acc2[8][4];
        #pragma unroll
        for (int i = 0; i < 8; i++)
            #pragma unroll
            for (int j = 0; j < 4; j++) acc2[i][j] = 0ULL;

        const float* qb = Qs + (ty * 8) * QS_STRIDE;
        const float* kb = Ks + 2 * tx;
        #pragma unroll 2
        for (int w = 0; w < 96; w += 2) {
            ull bp0[4], bp1[4];
            #pragma unroll
            for (int j = 0; j < 4; j++) {
                bp0[j] = *reinterpret_cast<const ull*>(&kb[(w    ) * KS_STRIDE + 64 * j]);
                bp1[j] = *reinterpret_cast<const ull*>(&kb[(w + 1) * KS_STRIDE + 64 * j]);
            }
            #pragma unroll
            for (int i = 0; i < 8; i++) {
                float q0, q1;
                unpack2(*reinterpret_cast<const ull*>(&qb[i * QS_STRIDE + w]), q0, q1);
                ull a0 = pack2(q0, q0);
                ull a1 = pack2(q1, q1);
                #pragma unroll
                for (int j = 0; j < 4; j++) {
                    ffma2(acc2[i][j], a0, bp0[j]);
                    ffma2(acc2[i][j], a1, bp1[j]);
                }
            }
        }

        // softmax per row (row fully inside one warp); normalized P kept in acc2
        #pragma unroll
        for (int i = 0; i < 8; i++) {
            float p[8];
            #pragma unroll
            for (int j = 0; j < 4; j++) unpack2(acc2[i][j], p[2 * j], p[2 * j + 1]);
            float m = p[0];
            #pragma unroll
            for (int j = 1; j < 8; j++) m = fmaxf(m, p[j]);
            #pragma unroll
            for (int off = 16; off > 0; off >>= 1)
                m = fmaxf(m, __shfl_xor_sync(0xffffffffu, m, off));
            float s = 0.f;
            #pragma unroll
            for (int j = 0; j < 8; j++) {
                float e = __expf((p[j] - m) * inv_s);
                p[j] = e;
                s += e;
            }
            #pragma unroll
            for (int off = 16; off > 0; off >>= 1)
                s += __shfl_xor_sync(0xffffffffu, s, off);
            float rs = 1.f / s;
            #pragma unroll
            for (int j = 0; j < 4; j++)
                acc2[i][j] = pack2(p[2 * j] * rs, p[2 * j + 1] * rs);
        }

        // two halves: store 64 P-rows, then O = P @ V for those rows
        float* Vb0 = Qs;
        float* Vb1 = Qs + 64 * QS_STRIDE;

        #pragma unroll 1
        for (int half = 0; half < 2; half++) {
            if ((ty >> 3) == half) {
                int rbase = (ty & 7) * 8;
                #pragma unroll
                for (int i = 0; i < 8; i++) {
                    int r = rbase + i;
                    #pragma unroll
                    for (int j = 0; j < 4; j++) {
                        float p0, p1;
                        unpack2(acc2[i][j], p0, p1);
                        Ps[(2 * tx + 64 * j    ) * PS_STRIDE + r] = p0;
                        Ps[(2 * tx + 64 * j + 1) * PS_STRIDE + r] = p1;
                    }
                }
            }

            // preload V chunk 0 (rows 0..63) into registers
            float vreg[12];
            #pragma unroll
            for (int u = 0; u < 12; u++) vreg[u] = V[tid + u * 512];
            __syncthreads();   // Ps visible; Qs free (S done / prior PV done)
            #pragma unroll
            for (int u = 0; u < 12; u++) {
                int idx = tid + u * 512;
                int dd = idx / 96, w = idx - dd * 96;
                Vb0[dd * QS_STRIDE + w] = vreg[u];
            }
            __syncthreads();

            ull acco2[2][3];
            #pragma unroll
            for (int ii = 0; ii < 2; ii++)
                #pragma unroll
                for (int j = 0; j < 3; j++) acco2[ii][j] = 0ULL;

            #pragma unroll 1
            for (int c = 0; c < 4; c++) {
                if (c < 3) {
                    #pragma unroll
                    for (int u = 0; u < 12; u++)
                        vreg[u] = V[(c + 1) * 6144 + tid + u * 512];
                }
                const float* pb = Ps + (c * 64) * PS_STRIDE + ty * 4;
                const float* vb = ((c & 1) ? Vb1 : Vb0) + tx;
                #pragma unroll 2
                for (int dd = 0; dd < 64; dd++) {
                    ull ap0 = *reinterpret_cast<const ull*>(&pb[dd * PS_STRIDE]);
                    ull ap1 = *reinterpret_cast<const ull*>(&pb[dd * PS_STRIDE + 2]);
                    #pragma unroll
                    for (int j = 0; j < 3; j++) {
                        float v = vb[dd * QS_STRIDE + 32 * j];
                        ull bv = pack2(v, v);
                        ffma2(acco2[0][j], ap0, bv);
                        ffma2(acco2[1][j], ap1, bv);
                    }
                }
                if (c < 3) {
                    float* Vw = (c & 1) ? Vb0 : Vb1;
                    #pragma unroll
                    for (int u = 0; u < 12; u++) {
                        int idx = tid + u * 512;
                        int dd = idx / 96, w = idx - dd * 96;
                        Vw[dd * QS_STRIDE + w] = vreg[u];
                    }
                }
                __syncthreads();
            }

            // write O rows (r0 + half*64 + ty*4 + {0..3}) as [B][C][H][W]
            float* ob = out + (size_t)b * C_SZ * HW + (size_t)h * W_SZ + tx;
            #pragma unroll
            for (int ii = 0; ii < 2; ii++) {
                int c = r0 + half * 64 + ty * 4 + 2 * ii;
                #pragma unroll
                for (int j = 0; j < 3; j++) {
                    float o0, o1;
                    unpack2(acco2[ii][j], o0, o1);
                    ob[(size_t)c       * HW + j * 32] = o0;
                    ob[(size_t)(c + 1) * HW + j * 32] = o1;
                }
            }
        }
    }
}

// ---------------- launch ----------------
extern "C" void kernel_launch(void* const* d_in, const int* in_sizes, int n_in,
                              void* d_out, int out_size)
{
    const float* x  = (const float*)d_in[0];
    const float* y  = (const float*)d_in[1];
    const float* wy = (const float*)d_in[2];
    const float* by = (const float*)d_in[3];
    const float* wq = (const float*)d_in[4];
    const float* bq = (const float*)d_in[5];
    const float* wk = (const float*)d_in[6];
    const float* bk = (const float*)d_in[7];
    const float* wv = (const float*)d_in[8];
    const float* bv = (const float*)d_in[9];
    float* out = (float*)d_out;

    cudaFuncSetAttribute(attn_kernel, cudaFuncAttributeMaxDynamicSharedMemorySize,
                         ATTN_SMEM_BYTES);

    prep_kernel<<<1, 256>>>(wy, by, wq, bq, wk, bk);
    upsample_kernel<<<(B_SZ * HW + 255) / 256, 256>>>(y);
    dim3 g(HW / 128, 768 / 128, B_SZ);   // (72, 6, 8)
    conv_gemm_kernel<<<g, 256>>>(x, wq, bq, wk, bk, wv, bv);
    attn_kernel<<<B_SZ * H_SZ, 512, ATTN_SMEM_BYTES>>>(out);
}

// round 12
// speedup vs baseline: 1.3116x; 1.0806x over previous
#include <cuda_runtime.h>
#include <math.h>

#define B_SZ 8
#define C_SZ 256
#define H_SZ 96
#define W_SZ 96
#define HW   (H_SZ * W_SZ)   // 9216

typedef unsigned long long ull;

// ---------------- packed f32x2 helpers (FFMA2 path) ----------------
__device__ __forceinline__ ull pack2(float x, float y) {
    ull r;
    asm("mov.b64 %0, {%1, %2};" : "=l"(r) : "f"(x), "f"(y));
    return r;
}
__device__ __forceinline__ void unpack2(ull v, float& x, float& y) {
    asm("mov.b64 {%0, %1}, %2;" : "=f"(x), "=f"(y) : "l"(v));
}
__device__ __forceinline__ void ffma2(ull& d, ull a, ull b) {
    asm("fma.rn.f32x2 %0, %1, %2, %3;" : "=l"(d) : "l"(a), "l"(b), "l"(d));
}

// ---------------- scratch ----------------
__device__ float g_yu[B_SZ * HW];
__device__ float g_Aq[C_SZ], g_Bq[C_SZ], g_Ak[C_SZ], g_Bk[C_SZ];
__device__ float g_q[(size_t)B_SZ * H_SZ * C_SZ * W_SZ];  // [B][H][C][W]
__device__ float g_k[(size_t)B_SZ * H_SZ * C_SZ * W_SZ];
__device__ float g_v[(size_t)B_SZ * H_SZ * C_SZ * W_SZ];

// ---------------- kernel 0: fold y-branch weights ----------------
__global__ void prep_kernel(const float* __restrict__ wy, const float* __restrict__ by,
                            const float* __restrict__ wq, const float* __restrict__ bq,
                            const float* __restrict__ wk, const float* __restrict__ bk)
{
    int c = threadIdx.x;
    const float* wqr = wq + c * C_SZ;
    const float* wkr = wk + c * C_SZ;
    float aq = 0.f, bqs = 0.f, ak = 0.f, bks = 0.f;
    for (int j = 0; j < C_SZ; j++) {
        float wyj = wy[j], byj = by[j];
        aq += wqr[j] * wyj;  bqs += wqr[j] * byj;
        ak += wkr[j] * wyj;  bks += wkr[j] * byj;
    }
    g_Aq[c] = aq;  g_Bq[c] = bqs + bq[c];
    g_Ak[c] = ak;  g_Bk[c] = bks + bk[c];
}

// ---------------- kernel 1: bilinear 24x24 -> 96x96 ----------------
__global__ void upsample_kernel(const float* __restrict__ y)
{
    int idx = blockIdx.x * blockDim.x + threadIdx.x;
    if (idx >= B_SZ * HW) return;
    int b  = idx / HW;
    int r  = idx - b * HW;
    int oh = r / W_SZ;
    int ow = r - oh * W_SZ;
    float sy = (oh + 0.5f) * 0.25f - 0.5f;
    float sx = (ow + 0.5f) * 0.25f - 0.5f;
    int y0 = (int)floorf(sy);  float fy = sy - (float)y0;
    int x0 = (int)floorf(sx);  float fx = sx - (float)x0;
    int y0c = max(0, min(23, y0)),     y1c = max(0, min(23, y0 + 1));
    int x0c = max(0, min(23, x0)),     x1c = max(0, min(23, x0 + 1));
    const float* yb = y + b * 576;
    float v00 = yb[y0c * 24 + x0c], v01 = yb[y0c * 24 + x1c];
    float v10 = yb[y1c * 24 + x0c], v11 = yb[y1c * 24 + x1c];
    g_yu[idx] = (1.f - fy) * ((1.f - fx) * v00 + fx * v01)
              +        fy  * ((1.f - fx) * v10 + fx * v11);
}

// ---------------- kernel 2: fused QKV conv as SGEMM (FFMA2, pack-in-loop) ----------------
__global__ __launch_bounds__(256, 2) void conv_gemm_kernel(
    const float* __restrict__ x,
    const float* __restrict__ wq, const float* __restrict__ bq,
    const float* __restrict__ wk, const float* __restrict__ bk,
    const float* __restrict__ wv, const float* __restrict__ bv)
{
    __shared__ __align__(16) float As[2][16][132];   // A tile transposed (k-major), padded
    __shared__ __align__(16) float Bs[2][16][128];

    int b  = blockIdx.z;
    int n0 = blockIdx.x * 128;
    int m0 = blockIdx.y * 128;
    int sel = m0 >> 8;                          // 0=q, 1=k, 2=v
    const float* W    = (sel == 0) ? wq : (sel == 1) ? wk : wv;
    const float* bias = (sel == 0) ? bq : (sel == 1) ? bk : bv;
    int mrow0 = m0 & 255;
    const float* Xb = x + (size_t)b * C_SZ * HW;

    int tid = threadIdx.x;
    int a_k = (tid & 3) * 4;
    int a_m = tid >> 2;          // 0..63
    int b_n = (tid & 31) * 4;
    int b_k = tid >> 5;          // 0..7
    int tx  = tid & 15, ty = tid >> 4;

    ull acc2[8][4];
    #pragma unroll
    for (int i = 0; i < 8; i++)
        #pragma unroll
        for (int j = 0; j < 4; j++) acc2[i][j] = 0ULL;

    auto load_tiles = [&](int k0, int buf) {
        #pragma unroll
        for (int p = 0; p < 2; p++) {
            int m = a_m + p * 64;
            float4 v = *reinterpret_cast<const float4*>(&W[(mrow0 + m) * C_SZ + k0 + a_k]);
            As[buf][a_k + 0][m] = v.x;
            As[buf][a_k + 1][m] = v.y;
            As[buf][a_k + 2][m] = v.z;
            As[buf][a_k + 3][m] = v.w;
        }
        #pragma unroll
        for (int p = 0; p < 2; p++) {
            int kk = b_k + p * 8;
            *reinterpret_cast<float4*>(&Bs[buf][kk][b_n]) =
                *reinterpret_cast<const float4*>(&Xb[(size_t)(k0 + kk) * HW + n0 + b_n]);
        }
    };

    load_tiles(0, 0);
    __syncthreads();

    #pragma unroll 1
    for (int kt = 0; kt < 16; kt++) {
        int buf = kt & 1;
        if (kt < 15) load_tiles((kt + 1) * 16, buf ^ 1);
        #pragma unroll
        for (int kk = 0; kk < 16; kk++) {
            longlong2 bl0 = *reinterpret_cast<const longlong2*>(&Bs[buf][kk][tx * 8]);
            longlong2 bl1 = *reinterpret_cast<const longlong2*>(&Bs[buf][kk][tx * 8 + 4]);
            ull bp[4];
            bp[0] = (ull)bl0.x; bp[1] = (ull)bl0.y;
            bp[2] = (ull)bl1.x; bp[3] = (ull)bl1.y;
            float4 a0 = *reinterpret_cast<const float4*>(&As[buf][kk][ty * 8]);
            float4 a1 = *reinterpret_cast<const float4*>(&As[buf][kk][ty * 8 + 4]);
            float av[8] = {a0.x, a0.y, a0.z, a0.w, a1.x, a1.y, a1.z, a1.w};
            #pragma unroll
            for (int i = 0; i < 8; i++) {
                ull aa = pack2(av[i], av[i]);
                #pragma unroll
                for (int j = 0; j < 4; j++)
                    ffma2(acc2[i][j], aa, bp[j]);
            }
        }
        __syncthreads();
    }

    float* outbuf = (sel == 0) ? g_q : (sel == 1) ? g_k : g_v;
    const float* Agp = (sel == 0) ? g_Aq : g_Ak;
    const float* Bgp = (sel == 0) ? g_Bq : g_Bk;
    const float* yub = g_yu + b * HW;

    float yuv[8];
    if (sel < 2) {
        #pragma unroll
        for (int j = 0; j < 8; j++) yuv[j] = yub[n0 + tx * 8 + j];
    }

    #pragma unroll
    for (int i = 0; i < 8; i++) {
        int c = mrow0 + ty * 8 + i;
        float bi = bias[c];
        float Ag = 0.f, Bg = 0.f;
        if (sel < 2) { Ag = Agp[c]; Bg = Bgp[c]; }
        float row[8];
        #pragma unroll
        for (int j = 0; j < 4; j++) unpack2(acc2[i][j], row[2 * j], row[2 * j + 1]);
        #pragma unroll
        for (int j = 0; j < 8; j++) {
            int n = n0 + tx * 8 + j;
            float val = row[j] + bi;
            if (sel < 2) val *= (yuv[j] * Ag + Bg);
            int h = n / 96;
            int w = n - h * 96;
            outbuf[(((size_t)b * H_SZ + h) * C_SZ + c) * W_SZ + w] = val;
        }
    }
}

// ---------------- kernel 3: channel attention, one CTA per 128-row tile ----------------
// Phase-union smem:
//   Phase A (S):  Ks [w][d] 96 x 260  at 0       (24960 floats)
//                 Qs [r][w] 128 x 98  at 24960   (12544 floats)  end 37504
//   Phase B (PV): Ps [dd][r] 256 x 130 at 0      (33280 floats)  (aliases Ks+Qs)
//                 Vs double buffer 2 x 64 x 98 at 33280 (12544)  end 45824
#define KSS 260
#define QSS 98
#define PSS 130
#define ATTN_SMEM_FLOATS (256 * PSS + 2 * 64 * QSS)   // 45824
#define ATTN_SMEM_BYTES  (ATTN_SMEM_FLOATS * 4)       // 183296

__global__ __launch_bounds__(512, 1) void attn_kernel(float* __restrict__ out)
{
    extern __shared__ __align__(16) float sm[];
    float* Ks  = sm;                   // phase A
    float* Qs  = sm + 96 * KSS;        // phase A
    float* Ps  = sm;                   // phase B (aliases Ks/Qs)
    float* Vs0 = sm + 256 * PSS;       // phase B
    float* Vs1 = Vs0 + 64 * QSS;

    int bid = blockIdx.x;              // 0..1535
    int bh  = bid >> 1;
    int t   = bid & 1;                 // which 128-row tile
    int b   = bh / H_SZ;
    int h   = bh - b * H_SZ;
    const float* Q = g_q + (size_t)bh * C_SZ * W_SZ + t * 128 * W_SZ;
    const float* K = g_k + (size_t)bh * C_SZ * W_SZ;
    const float* V = g_v + (size_t)bh * C_SZ * W_SZ;

    int tid = threadIdx.x;
    int ty  = tid >> 5;   // warp 0..15 -> 8 S-rows
    int tx  = tid & 31;   // lane -> col pairs {2tx+64j, 2tx+1+64j}

    // ---- phase A loads ----
    for (int idx = tid; idx < C_SZ * W_SZ; idx += 512) {
        int d = idx / W_SZ;
        int w = idx - d * W_SZ;
        Ks[w * KSS + d] = K[idx];
    }
    for (int idx = tid; idx < 128 * W_SZ; idx += 512) {
        int r = idx / W_SZ;
        int w = idx - r * W_SZ;
        Qs[r * QSS + w] = Q[idx];
    }
    __syncthreads();

    const float inv_s = 0.17677669529663687f;  // 1/sqrt(32)

    // ---- S = Q @ K^T (128 x 256), 8 rows/warp, 4 col-pairs/lane ----
    ull acc2[8][4];
    #pragma unroll
    for (int i = 0; i < 8; i++)
        #pragma unroll
        for (int j = 0; j < 4; j++) acc2[i][j] = 0ULL;

    {
        const float* qb = Qs + (ty * 8) * QSS;
        const float* kb = Ks + 2 * tx;
        #pragma unroll 2
        for (int w = 0; w < 96; w += 2) {
            ull bp0[4], bp1[4];
            #pragma unroll
            for (int j = 0; j < 4; j++) {
                bp0[j] = *reinterpret_cast<const ull*>(&kb[(w    ) * KSS + 64 * j]);
                bp1[j] = *reinterpret_cast<const ull*>(&kb[(w + 1) * KSS + 64 * j]);
            }
            #pragma unroll
            for (int i = 0; i < 8; i++) {
                float q0, q1;
                unpack2(*reinterpret_cast<const ull*>(&qb[i * QSS + w]), q0, q1);
                ull a0 = pack2(q0, q0);
                ull a1 = pack2(q1, q1);
                #pragma unroll
                for (int j = 0; j < 4; j++) {
                    ffma2(acc2[i][j], a0, bp0[j]);
                    ffma2(acc2[i][j], a1, bp1[j]);
                }
            }
        }
    }

    // ---- softmax per row (row inside one warp); normalized P kept in acc2 ----
    #pragma unroll
    for (int i = 0; i < 8; i++) {
        float p[8];
        #pragma unroll
        for (int j = 0; j < 4; j++) unpack2(acc2[i][j], p[2 * j], p[2 * j + 1]);
        float m = p[0];
        #pragma unroll
        for (int j = 1; j < 8; j++) m = fmaxf(m, p[j]);
        #pragma unroll
        for (int off = 16; off > 0; off >>= 1)
            m = fmaxf(m, __shfl_xor_sync(0xffffffffu, m, off));
        float s = 0.f;
        #pragma unroll
        for (int j = 0; j < 8; j++) {
            float e = __expf((p[j] - m) * inv_s);
            p[j] = e;
            s += e;
        }
        #pragma unroll
        for (int off = 16; off > 0; off >>= 1)
            s += __shfl_xor_sync(0xffffffffu, s, off);
        float rs = 1.f / s;
        #pragma unroll
        for (int j = 0; j < 4; j++)
            acc2[i][j] = pack2(p[2 * j] * rs, p[2 * j + 1] * rs);
    }

    __syncthreads();   // all Ks/Qs reads done before P overwrites them

    // ---- store P transposed [dd][r] with r-pair STS.64; prefetch V chunk 0 ----
    float vreg[12];
    #pragma unroll
    for (int u = 0; u < 12; u++) vreg[u] = V[tid + u * 512];

    {
        int rr = ty * 8;
        #pragma unroll
        for (int ii = 0; ii < 4; ii++) {
            #pragma unroll
            for (int j = 0; j < 4; j++) {
                float a0, a1, b0, b1;
                unpack2(acc2[2 * ii    ][j], a0, a1);
                unpack2(acc2[2 * ii + 1][j], b0, b1);
                int col = 2 * tx + 64 * j;
                *reinterpret_cast<ull*>(&Ps[(size_t)col       * PSS + rr + 2 * ii]) = pack2(a0, b0);
                *reinterpret_cast<ull*>(&Ps[(size_t)(col + 1) * PSS + rr + 2 * ii]) = pack2(a1, b1);
            }
        }
    }
    #pragma unroll
    for (int u = 0; u < 12; u++) {
        int idx = tid + u * 512;
        int dd = idx / 96, w = idx - dd * 96;
        Vs0[dd * QSS + w] = vreg[u];
    }
    __syncthreads();

    // ---- O = P @ V: warp -> 8 rows (4 bc pairs), lane -> 3 cols (tx+32j) ----
    ull acco2[4][3];
    #pragma unroll
    for (int ii = 0; ii < 4; ii++)
        #pragma unroll
        for (int j = 0; j < 3; j++) acco2[ii][j] = 0ULL;

    #pragma unroll 1
    for (int c = 0; c < 4; c++) {
        if (c < 3) {
            #pragma unroll
            for (int u = 0; u < 12; u++)
                vreg[u] = V[(c + 1) * 6144 + tid + u * 512];
        }
        const float* pb = Ps + (size_t)(c * 64) * PSS + ty * 8;
        const float* vb = ((c & 1) ? Vs1 : Vs0) + tx;
        #pragma unroll 2
        for (int dd = 0; dd < 64; dd++) {
            ull ap[4];
            #pragma unroll
            for (int ii = 0; ii < 4; ii++)
                ap[ii] = *reinterpret_cast<const ull*>(&pb[(size_t)dd * PSS + 2 * ii]);
            #pragma unroll
            for (int j = 0; j < 3; j++) {
                float v = vb[dd * QSS + 32 * j];
                ull bv = pack2(v, v);
                #pragma unroll
                for (int ii = 0; ii < 4; ii++)
                    ffma2(acco2[ii][j], ap[ii], bv);
            }
        }
        if (c < 3) {
            float* Vw = (c & 1) ? Vs0 : Vs1;
            #pragma unroll
            for (int u = 0; u < 12; u++) {
                int idx = tid + u * 512;
                int dd = idx / 96, w = idx - dd * 96;
                Vw[dd * QSS + w] = vreg[u];
            }
        }
        __syncthreads();
    }

    // ---- write O rows (t*128 + ty*8 + 2ii {+1}) as [B][C][H][W] ----
    float* ob = out + (size_t)b * C_SZ * HW + (size_t)h * W_SZ + tx;
    #pragma unroll
    for (int ii = 0; ii < 4; ii++) {
        int c0 = t * 128 + ty * 8 + 2 * ii;
        #pragma unroll
        for (int j = 0; j < 3; j++) {
            float o0, o1;
            unpack2(acco2[ii][j], o0, o1);
            ob[(size_t)c0       * HW + j * 32] = o0;
            ob[(size_t)(c0 + 1) * HW + j * 32] = o1;
        }
    }
}

// ---------------- launch ----------------
extern "C" void kernel_launch(void* const* d_in, const int* in_sizes, int n_in,
                              void* d_out, int out_size)
{
    const float* x  = (const float*)d_in[0];
    const float* y  = (const float*)d_in[1];
    const float* wy = (const float*)d_in[2];
    const float* by = (const float*)d_in[3];
    const float* wq = (const float*)d_in[4];
    const float* bq = (const float*)d_in[5];
    const float* wk = (const float*)d_in[6];
    const float* bk = (const float*)d_in[7];
    const float* wv = (const float*)d_in[8];
    const float* bv = (const float*)d_in[9];
    float* out = (float*)d_out;

    cudaFuncSetAttribute(attn_kernel, cudaFuncAttributeMaxDynamicSharedMemorySize,
                         ATTN_SMEM_BYTES);

    prep_kernel<<<1, 256>>>(wy, by, wq, bq, wk, bk);
    upsample_kernel<<<(B_SZ * HW + 255) / 256, 256>>>(y);
    dim3 g(HW / 128, 768 / 128, B_SZ);   // (72, 6, 8)
    conv_gemm_kernel<<<g, 256>>>(x, wq, bq, wk, bk, wv, bv);
    attn_kernel<<<2 * B_SZ * H_SZ, 512, ATTN_SMEM_BYTES>>>(out);
}

// round 15
// speedup vs baseline: 1.7642x; 1.3450x over previous
#include <cuda_runtime.h>
#include <cuda_bf16.h>
#include <math.h>
#include <stdint.h>

#define B_SZ 8
#define C_SZ 256
#define H_SZ 96
#define W_SZ 96
#define HW   (H_SZ * W_SZ)   // 9216

typedef unsigned long long ull;

// ---------------- packed f32x2 helpers (FFMA2 path, attn) ----------------
__device__ __forceinline__ ull pack2(float x, float y) {
    ull r;
    asm("mov.b64 %0, {%1, %2};" : "=l"(r) : "f"(x), "f"(y));
    return r;
}
__device__ __forceinline__ void unpack2(ull v, float& x, float& y) {
    asm("mov.b64 {%0, %1}, %2;" : "=f"(x), "=f"(y) : "l"(v));
}
__device__ __forceinline__ void ffma2(ull& d, ull a, ull b) {
    asm("fma.rn.f32x2 %0, %1, %2, %3;" : "=l"(d) : "l"(a), "l"(b), "l"(d));
}

// ---------------- mma.sync helpers (sm_80-class PTX; no 'a'-gated features) ----------------
__device__ __forceinline__ uint32_t smem_u32(const void* p) {
    uint32_t a;
    asm("{ .reg .u64 t; cvta.to.shared.u64 t, %1; cvt.u32.u64 %0, t; }" : "=r"(a) : "l"(p));
    return a;
}
__device__ __forceinline__ void ldsm_x4(uint32_t* r, uint32_t addr) {
    asm volatile("ldmatrix.sync.aligned.m8n8.x4.shared.b16 {%0,%1,%2,%3}, [%4];"
        : "=r"(r[0]), "=r"(r[1]), "=r"(r[2]), "=r"(r[3]) : "r"(addr));
}
__device__ __forceinline__ void ldsm_x4_t(uint32_t* r, uint32_t addr) {
    asm volatile("ldmatrix.sync.aligned.m8n8.x4.trans.shared.b16 {%0,%1,%2,%3}, [%4];"
        : "=r"(r[0]), "=r"(r[1]), "=r"(r[2]), "=r"(r[3]) : "r"(addr));
}
__device__ __forceinline__ void mma16816(float* c, const uint32_t* a, const uint32_t* b) {
    asm volatile("mma.sync.aligned.m16n8k16.row.col.f32.bf16.bf16.f32 "
        "{%0,%1,%2,%3}, {%4,%5,%6,%7}, {%8,%9}, {%0,%1,%2,%3};"
        : "+f"(c[0]), "+f"(c[1]), "+f"(c[2]), "+f"(c[3])
        : "r"(a[0]), "r"(a[1]), "r"(a[2]), "r"(a[3]), "r"(b[0]), "r"(b[1]));
}

// ---------------- scratch ----------------
__device__ float g_yu[B_SZ * HW];
__device__ float g_Aq[C_SZ], g_Bq[C_SZ], g_Ak[C_SZ], g_Bk[C_SZ];
__device__ float g_q[(size_t)B_SZ * H_SZ * C_SZ * W_SZ];  // [B][H][C][W]
__device__ float g_k[(size_t)B_SZ * H_SZ * C_SZ * W_SZ];
__device__ float g_v[(size_t)B_SZ * H_SZ * C_SZ * W_SZ];

// ---------------- kernel 0: fold y-branch weights ----------------
__global__ void prep_kernel(const float* __restrict__ wy, const float* __restrict__ by,
                            const float* __restrict__ wq, const float* __restrict__ bq,
                            const float* __restrict__ wk, const float* __restrict__ bk)
{
    int c = threadIdx.x;
    const float* wqr = wq + c * C_SZ;
    const float* wkr = wk + c * C_SZ;
    float aq = 0.f, bqs = 0.f, ak = 0.f, bks = 0.f;
    for (int j = 0; j < C_SZ; j++) {
        float wyj = wy[j], byj = by[j];
        aq += wqr[j] * wyj;  bqs += wqr[j] * byj;
        ak += wkr[j] * wyj;  bks += wkr[j] * byj;
    }
    g_Aq[c] = aq;  g_Bq[c] = bqs + bq[c];
    g_Ak[c] = ak;  g_Bk[c] = bks + bk[c];
}

// ---------------- kernel 1: bilinear 24x24 -> 96x96 ----------------
__global__ void upsample_kernel(const float* __restrict__ y)
{
    int idx = blockIdx.x * blockDim.x + threadIdx.x;
    if (idx >= B_SZ * HW) return;
    int b  = idx / HW;
    int r  = idx - b * HW;
    int oh = r / W_SZ;
    int ow = r - oh * W_SZ;
    float sy = (oh + 0.5f) * 0.25f - 0.5f;
    float sx = (ow + 0.5f) * 0.25f - 0.5f;
    int y0 = (int)floorf(sy);  float fy = sy - (float)y0;
    int x0 = (int)floorf(sx);  float fx = sx - (float)x0;
    int y0c = max(0, min(23, y0)),     y1c = max(0, min(23, y0 + 1));
    int x0c = max(0, min(23, x0)),     x1c = max(0, min(23, x0 + 1));
    const float* yb = y + b * 576;
    float v00 = yb[y0c * 24 + x0c], v01 = yb[y0c * 24 + x1c];
    float v10 = yb[y1c * 24 + x0c], v11 = yb[y1c * 24 + x1c];
    g_yu[idx] = (1.f - fy) * ((1.f - fx) * v00 + fx * v01)
              +        fy  * ((1.f - fx) * v10 + fx * v11);
}

// ---------------- kernel 2: fused QKV conv via mma.sync bf16 3-term split ----------------
// U[128m,128n] = Wsel[mrow0.., :256] @ X[:256, n0..] ; A=[m][k] smem, B natural [k][n] smem.
// 16 warps, each 32x32 (2 m-frags x 4 n-frags). K chunks of 64.
#define AS_STRIDE 72     // bf16 (144B: 16B-aligned, ldmatrix conflict-free)
#define BS_STRIDE 136    // bf16 (272B)
#define CV_AS_BYTES (128 * AS_STRIDE * 2)     // 18432
#define CV_BS_BYTES (64 * BS_STRIDE * 2)      // 17408
#define CV_SMEM_BYTES (2 * CV_AS_BYTES + 2 * CV_BS_BYTES)   // 71680

__global__ __launch_bounds__(512, 1) void conv_tensor_kernel(
    const float* __restrict__ x,
    const float* __restrict__ wq, const float* __restrict__ bq,
    const float* __restrict__ wk, const float* __restrict__ bk,
    const float* __restrict__ wv, const float* __restrict__ bv)
{
    extern __shared__ __align__(16) char dynsm[];
    __nv_bfloat16* Ah_s = (__nv_bfloat16*)dynsm;                         // [128][72]
    __nv_bfloat16* Al_s = (__nv_bfloat16*)(dynsm + CV_AS_BYTES);
    __nv_bfloat16* Bh_s = (__nv_bfloat16*)(dynsm + 2 * CV_AS_BYTES);     // [64][136]
    __nv_bfloat16* Bl_s = (__nv_bfloat16*)(dynsm + 2 * CV_AS_BYTES + CV_BS_BYTES);
    uint32_t uAh = smem_u32(Ah_s), uAl = smem_u32(Al_s);
    uint32_t uBh = smem_u32(Bh_s), uBl = smem_u32(Bl_s);

    int b  = blockIdx.z;
    int n0 = blockIdx.x * 128;
    int m0 = blockIdx.y * 128;
    int sel = m0 >> 8;
    const float* W    = (sel == 0) ? wq : (sel == 1) ? wk : wv;
    const float* bias = (sel == 0) ? bq : (sel == 1) ? bk : bv;
    int mrow0 = m0 & 255;
    const float* Xb = x + (size_t)b * C_SZ * HW;

    int tid  = threadIdx.x;
    int lane = tid & 31;
    int wid  = tid >> 5;
    int wm   = wid >> 2;      // 0..3 -> rows wm*32
    int wn   = wid & 3;       // 0..3 -> cols wn*32

    // per-thread ldmatrix address components
    int a_row = wm * 32 + (lane & 7) + ((lane >> 3) & 1) * 8;   // + mf*16
    int a_ko  = ((lane >> 4) & 1) * 8;                           // + kk
    int b_kr  = (lane & 7) + ((lane >> 3) & 1) * 8;              // + kk
    int b_nc  = wn * 32 + ((lane >> 4) & 1) * 8;                 // + half*16

    float acc[2][4][4];
    #pragma unroll
    for (int mf = 0; mf < 2; mf++)
        #pragma unroll
        for (int nf = 0; nf < 4; nf++)
            #pragma unroll
            for (int r = 0; r < 4; r++) acc[mf][nf][r] = 0.f;

    #pragma unroll 1
    for (int kc = 0; kc < 4; kc++) {
        __syncthreads();   // previous chunk's ldmatrix reads done
        // ---- stage A: W[mrow0+row][kc*64 + 2p..] -> hi/lo, [m][k] ----
        {
            const float* Wm = W + (size_t)mrow0 * C_SZ + kc * 64;
            #pragma unroll
            for (int u = 0; u < 8; u++) {
                int idx = tid + u * 512;
                int row = idx >> 5, p = idx & 31;
                float2 v = *reinterpret_cast<const float2*>(&Wm[row * C_SZ + 2 * p]);
                __nv_bfloat16 h0 = __float2bfloat16(v.x);
                __nv_bfloat16 h1 = __float2bfloat16(v.y);
                __nv_bfloat16 l0 = __float2bfloat16(v.x - __bfloat162float(h0));
                __nv_bfloat16 l1 = __float2bfloat16(v.y - __bfloat162float(h1));
                int o = row * AS_STRIDE + 2 * p;
                *reinterpret_cast<__nv_bfloat162*>(&Ah_s[o]) = __nv_bfloat162(h0, h1);
                *reinterpret_cast<__nv_bfloat162*>(&Al_s[o]) = __nv_bfloat162(l0, l1);
            }
        }
        // ---- stage B: X[kc*64+krow][n0 + 2p..] -> hi/lo, natural [k][n] ----
        {
            const float* Xm = Xb + (size_t)(kc * 64) * HW + n0;
            #pragma unroll
            for (int u = 0; u < 8; u++) {
                int idx = tid + u * 512;
                int krow = idx >> 6, p = idx & 63;
                float2 v = *reinterpret_cast<const float2*>(&Xm[(size_t)krow * HW + 2 * p]);
                __nv_bfloat16 h0 = __float2bfloat16(v.x);
                __nv_bfloat16 h1 = __float2bfloat16(v.y);
                __nv_bfloat16 l0 = __float2bfloat16(v.x - __bfloat162float(h0));
                __nv_bfloat16 l1 = __float2bfloat16(v.y - __bfloat162float(h1));
                int o = krow * BS_STRIDE + 2 * p;
                *reinterpret_cast<__nv_bfloat162*>(&Bh_s[o]) = __nv_bfloat162(h0, h1);
                *reinterpret_cast<__nv_bfloat162*>(&Bl_s[o]) = __nv_bfloat162(l0, l1);
            }
        }
        __syncthreads();

        // ---- mma over 4 k16-steps ----
        #pragma unroll
        for (int ks = 0; ks < 4; ks++) {
            int kk = ks * 16;
            uint32_t Ahf[2][4], Alf[2][4], Bhf[2][4], Blf[2][4];
            #pragma unroll
            for (int mf = 0; mf < 2; mf++) {
                uint32_t ao = (uint32_t)(((a_row + mf * 16) * AS_STRIDE + kk + a_ko) * 2);
                ldsm_x4(Ahf[mf], uAh + ao);
                ldsm_x4(Alf[mf], uAl + ao);
            }
            #pragma unroll
            for (int half = 0; half < 2; half++) {
                uint32_t bo = (uint32_t)(((kk + b_kr) * BS_STRIDE + b_nc + half * 16) * 2);
                ldsm_x4_t(Bhf[half], uBh + bo);
                ldsm_x4_t(Blf[half], uBl + bo);
            }
            #pragma unroll
            for (int mf = 0; mf < 2; mf++)
                #pragma unroll
                for (int nf = 0; nf < 4; nf++) {
                    const uint32_t* bh = &Bhf[nf >> 1][(nf & 1) * 2];
                    const uint32_t* bl = &Blf[nf >> 1][(nf & 1) * 2];
                    mma16816(acc[mf][nf], Ahf[mf], bh);   // hi*hi
                    mma16816(acc[mf][nf], Ahf[mf], bl);   // hi*lo
                    mma16816(acc[mf][nf], Alf[mf], bh);   // lo*hi
                }
        }
    }

    // ---- epilogue: bias + gate + paired stores (ng always even; pair never crosses w=96) ----
    float* outbuf = (sel == 0) ? g_q : (sel == 1) ? g_k : g_v;
    const float* Agp = (sel == 0) ? g_Aq : g_Ak;
    const float* Bgp = (sel == 0) ? g_Bq : g_Bk;
    const float* yub = g_yu + b * HW;

    int gid = lane >> 2, tig = lane & 3;
    #pragma unroll
    for (int mf = 0; mf < 2; mf++) {
        #pragma unroll
        for (int rh = 0; rh < 2; rh++) {
            int c = mrow0 + wm * 32 + mf * 16 + gid + rh * 8;
            float bi = bias[c];
            float Ag = 0.f, Bg = 0.f;
            if (sel < 2) { Ag = Agp[c]; Bg = Bgp[c]; }
            #pragma unroll
            for (int nf = 0; nf < 4; nf++) {
                int ng = n0 + wn * 32 + nf * 8 + 2 * tig;
                float v0 = acc[mf][nf][rh * 2 + 0] + bi;
                float v1 = acc[mf][nf][rh * 2 + 1] + bi;
                if (sel < 2) {
                    v0 *= (yub[ng]     * Ag + Bg);
                    v1 *= (yub[ng + 1] * Ag + Bg);
                }
                int h = ng / 96;
                int w = ng - h * 96;
                *reinterpret_cast<float2*>(
                    &outbuf[(((size_t)b * H_SZ + h) * C_SZ + c) * W_SZ + w]) =
                    make_float2(v0, v1);
            }
        }
    }
}

// ---------------- kernel 3: channel attention (R12, unchanged) ----------------
#define KSS 260
#define QSS 98
#define PSS 130
#define ATTN_SMEM_FLOATS (256 * PSS + 2 * 64 * QSS)   // 45824
#define ATTN_SMEM_BYTES  (ATTN_SMEM_FLOATS * 4)       // 183296

__global__ __launch_bounds__(512, 1) void attn_kernel(float* __restrict__ out)
{
    extern __shared__ __align__(16) float sm[];
    float* Ks  = sm;
    float* Qs  = sm + 96 * KSS;
    float* Ps  = sm;
    float* Vs0 = sm + 256 * PSS;
    float* Vs1 = Vs0 + 64 * QSS;

    int bid = blockIdx.x;
    int bh  = bid >> 1;
    int t   = bid & 1;
    int b   = bh / H_SZ;
    int h   = bh - b * H_SZ;
    const float* Q = g_q + (size_t)bh * C_SZ * W_SZ + t * 128 * W_SZ;
    const float* K = g_k + (size_t)bh * C_SZ * W_SZ;
    const float* V = g_v + (size_t)bh * C_SZ * W_SZ;

    int tid = threadIdx.x;
    int ty  = tid >> 5;
    int tx  = tid & 31;

    for (int idx = tid; idx < C_SZ * W_SZ; idx += 512) {
        int d = idx / W_SZ;
        int w = idx - d * W_SZ;
        Ks[w * KSS + d] = K[idx];
    }
    for (int idx = tid; idx < 128 * W_SZ; idx += 512) {
        int r = idx / W_SZ;
        int w = idx - r * W_SZ;
        Qs[r * QSS + w] = Q[idx];
    }
    __syncthreads();

    const float inv_s = 0.17677669529663687f;

    ull acc2[8][4];
    #pragma unroll
    for (int i = 0; i < 8; i++)
        #pragma unroll
        for (int j = 0; j < 4; j++) acc2[i][j] = 0ULL;

    {
        const float* qb = Qs + (ty * 8) * QSS;
        const float* kb = Ks + 2 * tx;
        #pragma unroll 2
        for (int w = 0; w < 96; w += 2) {
            ull bp0[4], bp1[4];
            #pragma unroll
            for (int j = 0; j < 4; j++) {
                bp0[j] = *reinterpret_cast<const ull*>(&kb[(w    ) * KSS + 64 * j]);
                bp1[j] = *reinterpret_cast<const ull*>(&kb[(w + 1) * KSS + 64 * j]);
            }
            #pragma unroll
            for (int i = 0; i < 8; i++) {
                float q0, q1;
                unpack2(*reinterpret_cast<const ull*>(&qb[i * QSS + w]), q0, q1);
                ull a0 = pack2(q0, q0);
                ull a1 = pack2(q1, q1);
                #pragma unroll
                for (int j = 0; j < 4; j++) {
                    ffma2(acc2[i][j], a0, bp0[j]);
                    ffma2(acc2[i][j], a1, bp1[j]);
                }
            }
        }
    }

    #pragma unroll
    for (int i = 0; i < 8; i++) {
        float p[8];
        #pragma unroll
        for (int j = 0; j < 4; j++) unpack2(acc2[i][j], p[2 * j], p[2 * j + 1]);
        float m = p[0];
        #pragma unroll
        for (int j = 1; j < 8; j++) m = fmaxf(m, p[j]);
        #pragma unroll
        for (int off = 16; off > 0; off >>= 1)
            m = fmaxf(m, __shfl_xor_sync(0xffffffffu, m, off));
        float s = 0.f;
        #pragma unroll
        for (int j = 0; j < 8; j++) {
            float e = __expf((p[j] - m) * inv_s);
            p[j] = e;
            s += e;
        }
        #pragma unroll
        for (int off = 16; off > 0; off >>= 1)
            s += __shfl_xor_sync(0xffffffffu, s, off);
        float rs = 1.f / s;
        #pragma unroll
        for (int j = 0; j < 4; j++)
            acc2[i][j] = pack2(p[2 * j] * rs, p[2 * j + 1] * rs);
    }

    __syncthreads();

    float vreg[12];
    #pragma unroll
    for (int u = 0; u < 12; u++) vreg[u] = V[tid + u * 512];

    {
        int rr = ty * 8;
        #pragma unroll
        for (int ii = 0; ii < 4; ii++) {
            #pragma unroll
            for (int j = 0; j < 4; j++) {
                float a0, a1, b0, b1;
                unpack2(acc2[2 * ii    ][j], a0, a1);
                unpack2(acc2[2 * ii + 1][j], b0, b1);
                int col = 2 * tx + 64 * j;
                *reinterpret_cast<ull*>(&Ps[(size_t)col       * PSS + rr + 2 * ii]) = pack2(a0, b0);
                *reinterpret_cast<ull*>(&Ps[(size_t)(col + 1) * PSS + rr + 2 * ii]) = pack2(a1, b1);
            }
        }
    }
    #pragma unroll
    for (int u = 0; u < 12; u++) {
        int idx = tid + u * 512;
        int dd = idx / 96, w = idx - dd * 96;
        Vs0[dd * QSS + w] = vreg[u];
    }
    __syncthreads();

    ull acco2[4][3];
    #pragma unroll
    for (int ii = 0; ii < 4; ii++)
        #pragma unroll
        for (int j = 0; j < 3; j++) acco2[ii][j] = 0ULL;

    #pragma unroll 1
    for (int c = 0; c < 4; c++) {
        if (c < 3) {
            #pragma unroll
            for (int u = 0; u < 12; u++)
                vreg[u] = V[(c + 1) * 6144 + tid + u * 512];
        }
        const float* pb = Ps + (size_t)(c * 64) * PSS + ty * 8;
        const float* vb = ((c & 1) ? Vs1 : Vs0) + tx;
        #pragma unroll 2
        for (int dd = 0; dd < 64; dd++) {
            ull ap[4];
            #pragma unroll
            for (int ii = 0; ii < 4; ii++)
                ap[ii] = *reinterpret_cast<const ull*>(&pb[(size_t)dd * PSS + 2 * ii]);
            #pragma unroll
            for (int j = 0; j < 3; j++) {
                float v = vb[dd * QSS + 32 * j];
                ull bv = pack2(v, v);
                #pragma unroll
                for (int ii = 0; ii < 4; ii++)
                    ffma2(acco2[ii][j], ap[ii], bv);
            }
        }
        if (c < 3) {
            float* Vw = (c & 1) ? Vs0 : Vs1;
            #pragma unroll
            for (int u = 0; u < 12; u++) {
                int idx = tid + u * 512;
                int dd = idx / 96, w = idx - dd * 96;
                Vw[dd * QSS + w] = vreg[u];
            }
        }
        __syncthreads();
    }

    float* ob = out + (size_t)b * C_SZ * HW + (size_t)h * W_SZ + tx;
    #pragma unroll
    for (int ii = 0; ii < 4; ii++) {
        int c0 = t * 128 + ty * 8 + 2 * ii;
        #pragma unroll
        for (int j = 0; j < 3; j++) {
            float o0, o1;
            unpack2(acco2[ii][j], o0, o1);
            ob[(size_t)c0       * HW + j * 32] = o0;
            ob[(size_t)(c0 + 1) * HW + j * 32] = o1;
        }
    }
}

// ---------------- launch ----------------
extern "C" void kernel_launch(void* const* d_in, const int* in_sizes, int n_in,
                              void* d_out, int out_size)
{
    const float* x  = (const float*)d_in[0];
    const float* y  = (const float*)d_in[1];
    const float* wy = (const float*)d_in[2];
    const float* by = (const float*)d_in[3];
    const float* wq = (const float*)d_in[4];
    const float* bq = (const float*)d_in[5];
    const float* wk = (const float*)d_in[6];
    const float* bk = (const float*)d_in[7];
    const float* wv = (const float*)d_in[8];
    const float* bv = (const float*)d_in[9];
    float* out = (float*)d_out;

    cudaFuncSetAttribute(attn_kernel, cudaFuncAttributeMaxDynamicSharedMemorySize,
                         ATTN_SMEM_BYTES);
    cudaFuncSetAttribute(conv_tensor_kernel, cudaFuncAttributeMaxDynamicSharedMemorySize,
                         CV_SMEM_BYTES);

    prep_kernel<<<1, 256>>>(wy, by, wq, bq, wk, bk);
    upsample_kernel<<<(B_SZ * HW + 255) / 256, 256>>>(y);
    dim3 g(HW / 128, 768 / 128, B_SZ);   // (72, 6, 8)
    conv_tensor_kernel<<<g, 512, CV_SMEM_BYTES>>>(x, wq, bq, wk, bk, wv, bv);
    attn_kernel<<<2 * B_SZ * H_SZ, 512, ATTN_SMEM_BYTES>>>(out);
}

// round 16
// speedup vs baseline: 2.7793x; 1.5754x over previous
#include <cuda_runtime.h>
#include <cuda_bf16.h>
#include <math.h>
#include <stdint.h>

#define B_SZ 8
#define C_SZ 256
#define H_SZ 96
#define W_SZ 96
#define HW   (H_SZ * W_SZ)   // 9216

typedef unsigned long long ull;

// ---------------- mma.sync helpers (sm_80-class PTX; no 'a'-gated features) ----------------
__device__ __forceinline__ uint32_t smem_u32(const void* p) {
    uint32_t a;
    asm("{ .reg .u64 t; cvta.to.shared.u64 t, %1; cvt.u32.u64 %0, t; }" : "=r"(a) : "l"(p));
    return a;
}
__device__ __forceinline__ void ldsm_x4(uint32_t* r, uint32_t addr) {
    asm volatile("ldmatrix.sync.aligned.m8n8.x4.shared.b16 {%0,%1,%2,%3}, [%4];"
        : "=r"(r[0]), "=r"(r[1]), "=r"(r[2]), "=r"(r[3]) : "r"(addr));
}
__device__ __forceinline__ void ldsm_x4_t(uint32_t* r, uint32_t addr) {
    asm volatile("ldmatrix.sync.aligned.m8n8.x4.trans.shared.b16 {%0,%1,%2,%3}, [%4];"
        : "=r"(r[0]), "=r"(r[1]), "=r"(r[2]), "=r"(r[3]) : "r"(addr));
}
__device__ __forceinline__ void mma16816(float* c, const uint32_t* a, const uint32_t* b) {
    asm volatile("mma.sync.aligned.m16n8k16.row.col.f32.bf16.bf16.f32 "
        "{%0,%1,%2,%3}, {%4,%5,%6,%7}, {%8,%9}, {%0,%1,%2,%3};"
        : "+f"(c[0]), "+f"(c[1]), "+f"(c[2]), "+f"(c[3])
        : "r"(a[0]), "r"(a[1]), "r"(a[2]), "r"(a[3]), "r"(b[0]), "r"(b[1]));
}
__device__ __forceinline__ void split_store2(__nv_bfloat16* hb, __nv_bfloat16* lb,
                                             int off, float x, float y) {
    __nv_bfloat16 h0 = __float2bfloat16(x), h1 = __float2bfloat16(y);
    __nv_bfloat16 l0 = __float2bfloat16(x - __bfloat162float(h0));
    __nv_bfloat16 l1 = __float2bfloat16(y - __bfloat162float(h1));
    *reinterpret_cast<__nv_bfloat162*>(&hb[off]) = __nv_bfloat162(h0, h1);
    *reinterpret_cast<__nv_bfloat162*>(&lb[off]) = __nv_bfloat162(l0, l1);
}

// ---------------- scratch ----------------
__device__ float g_yu[B_SZ * HW];
__device__ float g_Aq[C_SZ], g_Bq[C_SZ], g_Ak[C_SZ], g_Bk[C_SZ];
__device__ float g_q[(size_t)B_SZ * H_SZ * C_SZ * W_SZ];  // [B][H][C][W]
__device__ float g_k[(size_t)B_SZ * H_SZ * C_SZ * W_SZ];
__device__ float g_v[(size_t)B_SZ * H_SZ * C_SZ * W_SZ];

// ---------------- kernel 0: fold y-branch weights ----------------
__global__ void prep_kernel(const float* __restrict__ wy, const float* __restrict__ by,
                            const float* __restrict__ wq, const float* __restrict__ bq,
                            const float* __restrict__ wk, const float* __restrict__ bk)
{
    int c = threadIdx.x;
    const float* wqr = wq + c * C_SZ;
    const float* wkr = wk + c * C_SZ;
    float aq = 0.f, bqs = 0.f, ak = 0.f, bks = 0.f;
    for (int j = 0; j < C_SZ; j++) {
        float wyj = wy[j], byj = by[j];
        aq += wqr[j] * wyj;  bqs += wqr[j] * byj;
        ak += wkr[j] * wyj;  bks += wkr[j] * byj;
    }
    g_Aq[c] = aq;  g_Bq[c] = bqs + bq[c];
    g_Ak[c] = ak;  g_Bk[c] = bks + bk[c];
}

// ---------------- kernel 1: bilinear 24x24 -> 96x96 ----------------
__global__ void upsample_kernel(const float* __restrict__ y)
{
    int idx = blockIdx.x * blockDim.x + threadIdx.x;
    if (idx >= B_SZ * HW) return;
    int b  = idx / HW;
    int r  = idx - b * HW;
    int oh = r / W_SZ;
    int ow = r - oh * W_SZ;
    float sy = (oh + 0.5f) * 0.25f - 0.5f;
    float sx = (ow + 0.5f) * 0.25f - 0.5f;
    int y0 = (int)floorf(sy);  float fy = sy - (float)y0;
    int x0 = (int)floorf(sx);  float fx = sx - (float)x0;
    int y0c = max(0, min(23, y0)),     y1c = max(0, min(23, y0 + 1));
    int x0c = max(0, min(23, x0)),     x1c = max(0, min(23, x0 + 1));
    const float* yb = y + b * 576;
    float v00 = yb[y0c * 24 + x0c], v01 = yb[y0c * 24 + x1c];
    float v10 = yb[y1c * 24 + x0c], v11 = yb[y1c * 24 + x1c];
    g_yu[idx] = (1.f - fy) * ((1.f - fx) * v00 + fx * v01)
              +        fy  * ((1.f - fx) * v10 + fx * v11);
}

// ---------------- kernel 2: fused QKV conv via mma.sync bf16 3-term (R15, unchanged) ----------------
#define AS_STRIDE 72
#define BS_STRIDE 136
#define CV_AS_BYTES (128 * AS_STRIDE * 2)     // 18432
#define CV_BS_BYTES (64 * BS_STRIDE * 2)      // 17408
#define CV_SMEM_BYTES (2 * CV_AS_BYTES + 2 * CV_BS_BYTES)   // 71680

__global__ __launch_bounds__(512, 1) void conv_tensor_kernel(
    const float* __restrict__ x,
    const float* __restrict__ wq, const float* __restrict__ bq,
    const float* __restrict__ wk, const float* __restrict__ bk,
    const float* __restrict__ wv, const float* __restrict__ bv)
{
    extern __shared__ __align__(16) char dynsm[];
    __nv_bfloat16* Ah_s = (__nv_bfloat16*)dynsm;
    __nv_bfloat16* Al_s = (__nv_bfloat16*)(dynsm + CV_AS_BYTES);
    __nv_bfloat16* Bh_s = (__nv_bfloat16*)(dynsm + 2 * CV_AS_BYTES);
    __nv_bfloat16* Bl_s = (__nv_bfloat16*)(dynsm + 2 * CV_AS_BYTES + CV_BS_BYTES);
    uint32_t uAh = smem_u32(Ah_s), uAl = smem_u32(Al_s);
    uint32_t uBh = smem_u32(Bh_s), uBl = smem_u32(Bl_s);

    int b  = blockIdx.z;
    int n0 = blockIdx.x * 128;
    int m0 = blockIdx.y * 128;
    int sel = m0 >> 8;
    const float* W    = (sel == 0) ? wq : (sel == 1) ? wk : wv;
    const float* bias = (sel == 0) ? bq : (sel == 1) ? bk : bv;
    int mrow0 = m0 & 255;
    const float* Xb = x + (size_t)b * C_SZ * HW;

    int tid  = threadIdx.x;
    int lane = tid & 31;
    int wid  = tid >> 5;
    int wm   = wid >> 2;
    int wn   = wid & 3;

    int a_row = wm * 32 + (lane & 7) + ((lane >> 3) & 1) * 8;
    int a_ko  = ((lane >> 4) & 1) * 8;
    int b_kr  = (lane & 7) + ((lane >> 3) & 1) * 8;
    int b_nc  = wn * 32 + ((lane >> 4) & 1) * 8;

    float acc[2][4][4];
    #pragma unroll
    for (int mf = 0; mf < 2; mf++)
        #pragma unroll
        for (int nf = 0; nf < 4; nf++)
            #pragma unroll
            for (int r = 0; r < 4; r++) acc[mf][nf][r] = 0.f;

    #pragma unroll 1
    for (int kc = 0; kc < 4; kc++) {
        __syncthreads();
        {
            const float* Wm = W + (size_t)mrow0 * C_SZ + kc * 64;
            #pragma unroll
            for (int u = 0; u < 8; u++) {
                int idx = tid + u * 512;
                int row = idx >> 5, p = idx & 31;
                float2 v = *reinterpret_cast<const float2*>(&Wm[row * C_SZ + 2 * p]);
                split_store2(Ah_s, Al_s, row * AS_STRIDE + 2 * p, v.x, v.y);
            }
        }
        {
            const float* Xm = Xb + (size_t)(kc * 64) * HW + n0;
            #pragma unroll
            for (int u = 0; u < 8; u++) {
                int idx = tid + u * 512;
                int krow = idx >> 6, p = idx & 63;
                float2 v = *reinterpret_cast<const float2*>(&Xm[(size_t)krow * HW + 2 * p]);
                split_store2(Bh_s, Bl_s, krow * BS_STRIDE + 2 * p, v.x, v.y);
            }
        }
        __syncthreads();

        #pragma unroll
        for (int ks = 0; ks < 4; ks++) {
            int kk = ks * 16;
            uint32_t Ahf[2][4], Alf[2][4], Bhf[2][4], Blf[2][4];
            #pragma unroll
            for (int mf = 0; mf < 2; mf++) {
                uint32_t ao = (uint32_t)(((a_row + mf * 16) * AS_STRIDE + kk + a_ko) * 2);
                ldsm_x4(Ahf[mf], uAh + ao);
                ldsm_x4(Alf[mf], uAl + ao);
            }
            #pragma unroll
            for (int half = 0; half < 2; half++) {
                uint32_t bo = (uint32_t)(((kk + b_kr) * BS_STRIDE + b_nc + half * 16) * 2);
                ldsm_x4_t(Bhf[half], uBh + bo);
                ldsm_x4_t(Blf[half], uBl + bo);
            }
            #pragma unroll
            for (int mf = 0; mf < 2; mf++)
                #pragma unroll
                for (int nf = 0; nf < 4; nf++) {
                    const uint32_t* bh = &Bhf[nf >> 1][(nf & 1) * 2];
                    const uint32_t* bl = &Blf[nf >> 1][(nf & 1) * 2];
                    mma16816(acc[mf][nf], Ahf[mf], bh);
                    mma16816(acc[mf][nf], Ahf[mf], bl);
                    mma16816(acc[mf][nf], Alf[mf], bh);
                }
        }
    }

    float* outbuf = (sel == 0) ? g_q : (sel == 1) ? g_k : g_v;
    const float* Agp = (sel == 0) ? g_Aq : g_Ak;
    const float* Bgp = (sel == 0) ? g_Bq : g_Bk;
    const float* yub = g_yu + b * HW;

    int gid = lane >> 2, tig = lane & 3;
    #pragma unroll
    for (int mf = 0; mf < 2; mf++) {
        #pragma unroll
        for (int rh = 0; rh < 2; rh++) {
            int c = mrow0 + wm * 32 + mf * 16 + gid + rh * 8;
            float bi = bias[c];
            float Ag = 0.f, Bg = 0.f;
            if (sel < 2) { Ag = Agp[c]; Bg = Bgp[c]; }
            #pragma unroll
            for (int nf = 0; nf < 4; nf++) {
                int ng = n0 + wn * 32 + nf * 8 + 2 * tig;
                float v0 = acc[mf][nf][rh * 2 + 0] + bi;
                float v1 = acc[mf][nf][rh * 2 + 1] + bi;
                if (sel < 2) {
                    v0 *= (yub[ng]     * Ag + Bg);
                    v1 *= (yub[ng + 1] * Ag + Bg);
                }
                int h = ng / 96;
                int w = ng - h * 96;
                *reinterpret_cast<float2*>(
                    &outbuf[(((size_t)b * H_SZ + h) * C_SZ + c) * W_SZ + w]) =
                    make_float2(v0, v1);
            }
        }
    }
}

// ---------------- kernel 3: channel attention via mma.sync bf16 3-term ----------------
// Phase A: Qhi/Qlo [128][104] bf16, Khi/Klo [256][104]  (K natural [n][k] -> non-trans ldsm)
// Phase B (aliases A): Phi/Plo [128][264], V chunk hi/lo [128][104], red arrays.
#define oQh 0
#define oQl 13312
#define oKh 26624
#define oKl 53248
#define oPh 0
#define oPl 33792
#define oVh 67584
#define oVl 80896
#define RED_OFF 188416
#define ATT_SMEM_BYTES 190464

__global__ __launch_bounds__(512, 1) void attn_kernel(float* __restrict__ out)
{
    extern __shared__ __align__(16) char dynsm[];
    __nv_bfloat16* sb = (__nv_bfloat16*)dynsm;
    float* red_max = (float*)(dynsm + RED_OFF);
    float* red_sum = red_max + 256;
    uint32_t u0 = smem_u32(dynsm);

    int bid = blockIdx.x;              // 0..1535
    int bh  = bid >> 1;
    int t   = bid & 1;
    int b   = bh / H_SZ;
    int h   = bh - b * H_SZ;
    const float* Q = g_q + (size_t)bh * C_SZ * W_SZ + (size_t)t * 128 * W_SZ;
    const float* K = g_k + (size_t)bh * C_SZ * W_SZ;
    const float* V = g_v + (size_t)bh * C_SZ * W_SZ;

    int tid  = threadIdx.x;
    int lane = tid & 31;
    int wid  = tid >> 5;
    int wm2  = wid >> 1;      // 0..7  (16 rows each)
    int wn2  = wid & 1;       // 0..1
    int gid  = lane >> 2;
    int tig  = lane & 3;

    // ldmatrix lane address components (proven conv pattern)
    int arow = (lane & 7) + ((lane >> 3) & 1) * 8;   // A / P row-within-frag
    int ako  = ((lane >> 4) & 1) * 8;                // A / P k-offset
    int bno  = (lane & 7) + ((lane >> 4) & 1) * 8;   // S-B: n-row offset
    int bko  = ((lane >> 3) & 1) * 8;                // S-B: k-offset
    int vkr  = (lane & 7) + ((lane >> 3) & 1) * 8;   // PV-B (trans): k-row offset
    int vno  = ((lane >> 4) & 1) * 8;                // PV-B: n-offset

    // ---- stage Q [128][96] and K [256][96] hi/lo ----
    #pragma unroll
    for (int u = 0; u < 12; u++) {
        int f2i = tid + u * 512;
        int r = f2i / 48, p = f2i - r * 48;
        float2 v = *reinterpret_cast<const float2*>(&Q[r * 96 + 2 * p]);
        split_store2(sb + oQh, sb + oQl, r * 104 + 2 * p, v.x, v.y);
    }
    #pragma unroll
    for (int u = 0; u < 24; u++) {
        int f2i = tid + u * 512;
        int r = f2i / 48, p = f2i - r * 48;
        float2 v = *reinterpret_cast<const float2*>(&K[r * 96 + 2 * p]);
        split_store2(sb + oKh, sb + oKl, r * 104 + 2 * p, v.x, v.y);
    }
    __syncthreads();

    // ---- S = Q @ K^T : warp (wm2, wn2) -> rows wm2*16+16, cols wn2*128+128 ----
    float acc[16][4];
    #pragma unroll
    for (int nf = 0; nf < 16; nf++)
        #pragma unroll
        for (int r = 0; r < 4; r++) acc[nf][r] = 0.f;

    #pragma unroll 1
    for (int ks = 0; ks < 6; ks++) {
        uint32_t Ah[4], Al[4];
        uint32_t aoff = (uint32_t)(((wm2 * 16 + arow) * 104 + ks * 16 + ako) * 2);
        ldsm_x4(Ah, u0 + oQh * 2 + aoff);
        ldsm_x4(Al, u0 + oQl * 2 + aoff);
        #pragma unroll
        for (int nfp = 0; nfp < 8; nfp++) {
            int n = wn2 * 128 + nfp * 16 + bno;
            uint32_t boff = (uint32_t)((n * 104 + ks * 16 + bko) * 2);
            uint32_t Bh[4], Bl[4];
            ldsm_x4(Bh, u0 + oKh * 2 + boff);
            ldsm_x4(Bl, u0 + oKl * 2 + boff);
            #pragma unroll
            for (int sub = 0; sub < 2; sub++) {
                float* c = acc[nfp * 2 + sub];
                mma16816(c, Ah, &Bh[sub * 2]);
                mma16816(c, Ah, &Bl[sub * 2]);
                mma16816(c, Al, &Bh[sub * 2]);
            }
        }
    }

    // ---- softmax: rows split across wn2=0/1; reduce via quad-shfl + smem ----
    const float inv_s = 0.17677669529663687f;  // 1/sqrt(32)
    float gm[2], rs_[2];

    #pragma unroll
    for (int rh = 0; rh < 2; rh++) {
        float m = -1e30f;
        #pragma unroll
        for (int nf = 0; nf < 16; nf++)
            m = fmaxf(m, fmaxf(acc[nf][rh * 2], acc[nf][rh * 2 + 1]));
        m = fmaxf(m, __shfl_xor_sync(0xffffffffu, m, 1));
        m = fmaxf(m, __shfl_xor_sync(0xffffffffu, m, 2));
        if (tig == 0) red_max[(wm2 * 16 + gid + rh * 8) * 2 + wn2] = m;
    }
    __syncthreads();
    #pragma unroll
    for (int rh = 0; rh < 2; rh++) {
        int r = wm2 * 16 + gid + rh * 8;
        gm[rh] = fmaxf(red_max[r * 2], red_max[r * 2 + 1]);
    }
    #pragma unroll
    for (int rh = 0; rh < 2; rh++) {
        float s = 0.f;
        #pragma unroll
        for (int nf = 0; nf < 16; nf++) {
            float e0 = __expf((acc[nf][rh * 2]     - gm[rh]) * inv_s);
            float e1 = __expf((acc[nf][rh * 2 + 1] - gm[rh]) * inv_s);
            acc[nf][rh * 2] = e0;  acc[nf][rh * 2 + 1] = e1;
            s += e0 + e1;
        }
        s += __shfl_xor_sync(0xffffffffu, s, 1);
        s += __shfl_xor_sync(0xffffffffu, s, 2);
        if (tig == 0) red_sum[(wm2 * 16 + gid + rh * 8) * 2 + wn2] = s;
    }
    __syncthreads();
    #pragma unroll
    for (int rh = 0; rh < 2; rh++) {
        int r = wm2 * 16 + gid + rh * 8;
        rs_[rh] = 1.f / (red_sum[r * 2] + red_sum[r * 2 + 1]);
    }

    // ---- store P (normalized) hi/lo [m][k=256], stride 264; stage V chunk 0 ----
    #pragma unroll
    for (int rh = 0; rh < 2; rh++) {
        int r = wm2 * 16 + gid + rh * 8;
        float rr = rs_[rh];
        #pragma unroll
        for (int nf = 0; nf < 16; nf++) {
            int col = wn2 * 128 + nf * 8 + 2 * tig;
            split_store2(sb + oPh, sb + oPl, r * 264 + col,
                         acc[nf][rh * 2] * rr, acc[nf][rh * 2 + 1] * rr);
        }
    }
    #pragma unroll
    for (int u = 0; u < 12; u++) {
        int f2i = tid + u * 512;
        int r = f2i / 48, p = f2i - r * 48;
        float2 v = *reinterpret_cast<const float2*>(&V[r * 96 + 2 * p]);
        split_store2(sb + oVh, sb + oVl, r * 104 + 2 * p, v.x, v.y);
    }
    __syncthreads();

    // ---- O = P @ V : warp (wm2, wn2) -> rows wm2*16+16, cols wn2*48+48 ----
    float ao[6][4];
    #pragma unroll
    for (int nf = 0; nf < 6; nf++)
        #pragma unroll
        for (int r = 0; r < 4; r++) ao[nf][r] = 0.f;

    #pragma unroll 1
    for (int c = 0; c < 2; c++) {
        if (c == 1) {
            __syncthreads();   // chunk0 reads done
            #pragma unroll
            for (int u = 0; u < 12; u++) {
                int f2i = tid + u * 512;
                int r = f2i / 48, p = f2i - r * 48;
                float2 v = *reinterpret_cast<const float2*>(&V[(128 + r) * 96 + 2 * p]);
                split_store2(sb + oVh, sb + oVl, r * 104 + 2 * p, v.x, v.y);
            }
            __syncthreads();
        }
        #pragma unroll
        for (int ks = 0; ks < 8; ks++) {
            uint32_t Ph[4], Pl[4];
            uint32_t poff = (uint32_t)(((wm2 * 16 + arow) * 264 + c * 128 + ks * 16 + ako) * 2);
            ldsm_x4(Ph, u0 + oPh * 2 + poff);
            ldsm_x4(Pl, u0 + oPl * 2 + poff);
            #pragma unroll
            for (int nfp = 0; nfp < 3; nfp++) {
                int krow = ks * 16 + vkr;
                int n = wn2 * 48 + nfp * 16 + vno;
                uint32_t voff = (uint32_t)((krow * 104 + n) * 2);
                uint32_t Vh[4], Vl[4];
                ldsm_x4_t(Vh, u0 + oVh * 2 + voff);
                ldsm_x4_t(Vl, u0 + oVl * 2 + voff);
                #pragma unroll
                for (int sub = 0; sub < 2; sub++) {
                    float* cc = ao[nfp * 2 + sub];
                    mma16816(cc, Ph, &Vh[sub * 2]);
                    mma16816(cc, Ph, &Vl[sub * 2]);
                    mma16816(cc, Pl, &Vh[sub * 2]);
                }
            }
        }
    }

    // ---- write O rows (channels) as [B][C][H][W], paired stores ----
    #pragma unroll
    for (int rh = 0; rh < 2; rh++) {
        int r = wm2 * 16 + gid + rh * 8;
        int ch = t * 128 + r;
        float* ob = out + ((size_t)b * C_SZ + ch) * HW + (size_t)h * W_SZ;
        #pragma unroll
        for (int nf = 0; nf < 6; nf++) {
            int col = wn2 * 48 + nf * 8 + 2 * tig;
            *reinterpret_cast<float2*>(&ob[col]) =
                make_float2(ao[nf][rh * 2], ao[nf][rh * 2 + 1]);
        }
    }
}

// ---------------- launch ----------------
extern "C" void kernel_launch(void* const* d_in, const int* in_sizes, int n_in,
                              void* d_out, int out_size)
{
    const float* x  = (const float*)d_in[0];
    const float* y  = (const float*)d_in[1];
    const float* wy = (const float*)d_in[2];
    const float* by = (const float*)d_in[3];
    const float* wq = (const float*)d_in[4];
    const float* bq = (const float*)d_in[5];
    const float* wk = (const float*)d_in[6];
    const float* bk = (const float*)d_in[7];
    const float* wv = (const float*)d_in[8];
    const float* bv = (const float*)d_in[9];
    float* out = (float*)d_out;

    cudaFuncSetAttribute(attn_kernel, cudaFuncAttributeMaxDynamicSharedMemorySize,
                         ATT_SMEM_BYTES);
    cudaFuncSetAttribute(conv_tensor_kernel, cudaFuncAttributeMaxDynamicSharedMemorySize,
                         CV_SMEM_BYTES);

    prep_kernel<<<1, 256>>>(wy, by, wq, bq, wk, bk);
    upsample_kernel<<<(B_SZ * HW + 255) / 256, 256>>>(y);
    dim3 g(HW / 128, 768 / 128, B_SZ);   // (72, 6, 8)
    conv_tensor_kernel<<<g, 512, CV_SMEM_BYTES>>>(x, wq, bq, wk, bk, wv, bv);
    attn_kernel<<<2 * B_SZ * H_SZ, 512, ATT_SMEM_BYTES>>>(out);
}

// round 17
// speedup vs baseline: 2.7955x; 1.0058x over previous
#include <cuda_runtime.h>
#include <cuda_bf16.h>
#include <math.h>
#include <stdint.h>

#define B_SZ 8
#define C_SZ 256
#define H_SZ 96
#define W_SZ 96
#define HW   (H_SZ * W_SZ)   // 9216

typedef unsigned long long ull;

// ---------------- mma.sync helpers (sm_80-class PTX; no 'a'-gated features) ----------------
__device__ __forceinline__ uint32_t smem_u32(const void* p) {
    uint32_t a;
    asm("{ .reg .u64 t; cvta.to.shared.u64 t, %1; cvt.u32.u64 %0, t; }" : "=r"(a) : "l"(p));
    return a;
}
__device__ __forceinline__ void ldsm_x4(uint32_t* r, uint32_t addr) {
    asm volatile("ldmatrix.sync.aligned.m8n8.x4.shared.b16 {%0,%1,%2,%3}, [%4];"
        : "=r"(r[0]), "=r"(r[1]), "=r"(r[2]), "=r"(r[3]) : "r"(addr));
}
__device__ __forceinline__ void ldsm_x4_t(uint32_t* r, uint32_t addr) {
    asm volatile("ldmatrix.sync.aligned.m8n8.x4.trans.shared.b16 {%0,%1,%2,%3}, [%4];"
        : "=r"(r[0]), "=r"(r[1]), "=r"(r[2]), "=r"(r[3]) : "r"(addr));
}
__device__ __forceinline__ void mma16816(float* c, const uint32_t* a, const uint32_t* b) {
    asm volatile("mma.sync.aligned.m16n8k16.row.col.f32.bf16.bf16.f32 "
        "{%0,%1,%2,%3}, {%4,%5,%6,%7}, {%8,%9}, {%0,%1,%2,%3};"
        : "+f"(c[0]), "+f"(c[1]), "+f"(c[2]), "+f"(c[3])
        : "r"(a[0]), "r"(a[1]), "r"(a[2]), "r"(a[3]), "r"(b[0]), "r"(b[1]));
}
__device__ __forceinline__ void split_store2(__nv_bfloat16* hb, __nv_bfloat16* lb,
                                             int off, float x, float y) {
    __nv_bfloat16 h0 = __float2bfloat16(x), h1 = __float2bfloat16(y);
    __nv_bfloat16 l0 = __float2bfloat16(x - __bfloat162float(h0));
    __nv_bfloat16 l1 = __float2bfloat16(y - __bfloat162float(h1));
    *reinterpret_cast<__nv_bfloat162*>(&hb[off]) = __nv_bfloat162(h0, h1);
    *reinterpret_cast<__nv_bfloat162*>(&lb[off]) = __nv_bfloat162(l0, l1);
}

// ---------------- scratch ----------------
__device__ float g_yu[B_SZ * HW];
__device__ float g_Aq[C_SZ], g_Bq[C_SZ], g_Ak[C_SZ], g_Bk[C_SZ];
__device__ float g_q[(size_t)B_SZ * H_SZ * C_SZ * W_SZ];  // [B][H][C][W]
__device__ float g_k[(size_t)B_SZ * H_SZ * C_SZ * W_SZ];
__device__ float g_v[(size_t)B_SZ * H_SZ * C_SZ * W_SZ];

// ---------------- kernel 0: fold y-branch weights ----------------
__global__ void prep_kernel(const float* __restrict__ wy, const float* __restrict__ by,
                            const float* __restrict__ wq, const float* __restrict__ bq,
                            const float* __restrict__ wk, const float* __restrict__ bk)
{
    int c = threadIdx.x;
    const float* wqr = wq + c * C_SZ;
    const float* wkr = wk + c * C_SZ;
    float aq = 0.f, bqs = 0.f, ak = 0.f, bks = 0.f;
    for (int j = 0; j < C_SZ; j++) {
        float wyj = wy[j], byj = by[j];
        aq += wqr[j] * wyj;  bqs += wqr[j] * byj;
        ak += wkr[j] * wyj;  bks += wkr[j] * byj;
    }
    g_Aq[c] = aq;  g_Bq[c] = bqs + bq[c];
    g_Ak[c] = ak;  g_Bk[c] = bks + bk[c];
}

// ---------------- kernel 1: bilinear 24x24 -> 96x96 ----------------
__global__ void upsample_kernel(const float* __restrict__ y)
{
    int idx = blockIdx.x * blockDim.x + threadIdx.x;
    if (idx >= B_SZ * HW) return;
    int b  = idx / HW;
    int r  = idx - b * HW;
    int oh = r / W_SZ;
    int ow = r - oh * W_SZ;
    float sy = (oh + 0.5f) * 0.25f - 0.5f;
    float sx = (ow + 0.5f) * 0.25f - 0.5f;
    int y0 = (int)floorf(sy);  float fy = sy - (float)y0;
    int x0 = (int)floorf(sx);  float fx = sx - (float)x0;
    int y0c = max(0, min(23, y0)),     y1c = max(0, min(23, y0 + 1));
    int x0c = max(0, min(23, x0)),     x1c = max(0, min(23, x0 + 1));
    const float* yb = y + b * 576;
    float v00 = yb[y0c * 24 + x0c], v01 = yb[y0c * 24 + x1c];
    float v10 = yb[y1c * 24 + x0c], v11 = yb[y1c * 24 + x1c];
    g_yu[idx] = (1.f - fy) * ((1.f - fx) * v00 + fx * v01)
              +        fy  * ((1.f - fx) * v10 + fx * v11);
}

// ---------------- kernel 2: fused QKV conv, mma.sync 3-term, term-major order ----------------
#define AS_STRIDE 72
#define BS_STRIDE 136
#define CV_AS_BYTES (128 * AS_STRIDE * 2)     // 18432
#define CV_BS_BYTES (64 * BS_STRIDE * 2)      // 17408
#define CV_SMEM_BYTES (2 * CV_AS_BYTES + 2 * CV_BS_BYTES)   // 71680

__global__ __launch_bounds__(512, 1) void conv_tensor_kernel(
    const float* __restrict__ x,
    const float* __restrict__ wq, const float* __restrict__ bq,
    const float* __restrict__ wk, const float* __restrict__ bk,
    const float* __restrict__ wv, const float* __restrict__ bv)
{
    extern __shared__ __align__(16) char dynsm[];
    __nv_bfloat16* Ah_s = (__nv_bfloat16*)dynsm;
    __nv_bfloat16* Al_s = (__nv_bfloat16*)(dynsm + CV_AS_BYTES);
    __nv_bfloat16* Bh_s = (__nv_bfloat16*)(dynsm + 2 * CV_AS_BYTES);
    __nv_bfloat16* Bl_s = (__nv_bfloat16*)(dynsm + 2 * CV_AS_BYTES + CV_BS_BYTES);
    uint32_t uAh = smem_u32(Ah_s), uAl = smem_u32(Al_s);
    uint32_t uBh = smem_u32(Bh_s), uBl = smem_u32(Bl_s);

    int b  = blockIdx.z;
    int n0 = blockIdx.x * 128;
    int m0 = blockIdx.y * 128;
    int sel = m0 >> 8;
    const float* W    = (sel == 0) ? wq : (sel == 1) ? wk : wv;
    const float* bias = (sel == 0) ? bq : (sel == 1) ? bk : bv;
    int mrow0 = m0 & 255;
    const float* Xb = x + (size_t)b * C_SZ * HW;

    int tid  = threadIdx.x;
    int lane = tid & 31;
    int wid  = tid >> 5;
    int wm   = wid >> 2;
    int wn   = wid & 3;

    int a_row = wm * 32 + (lane & 7) + ((lane >> 3) & 1) * 8;
    int a_ko  = ((lane >> 4) & 1) * 8;
    int b_kr  = (lane & 7) + ((lane >> 3) & 1) * 8;
    int b_nc  = wn * 32 + ((lane >> 4) & 1) * 8;

    float acc[2][4][4];
    #pragma unroll
    for (int mf = 0; mf < 2; mf++)
        #pragma unroll
        for (int nf = 0; nf < 4; nf++)
            #pragma unroll
            for (int r = 0; r < 4; r++) acc[mf][nf][r] = 0.f;

    #pragma unroll 1
    for (int kc = 0; kc < 4; kc++) {
        __syncthreads();
        {
            const float* Wm = W + (size_t)mrow0 * C_SZ + kc * 64;
            #pragma unroll
            for (int u = 0; u < 8; u++) {
                int idx = tid + u * 512;
                int row = idx >> 5, p = idx & 31;
                float2 v = *reinterpret_cast<const float2*>(&Wm[row * C_SZ + 2 * p]);
                split_store2(Ah_s, Al_s, row * AS_STRIDE + 2 * p, v.x, v.y);
            }
        }
        {
            const float* Xm = Xb + (size_t)(kc * 64) * HW + n0;
            #pragma unroll
            for (int u = 0; u < 8; u++) {
                int idx = tid + u * 512;
                int krow = idx >> 6, p = idx & 63;
                float2 v = *reinterpret_cast<const float2*>(&Xm[(size_t)krow * HW + 2 * p]);
                split_store2(Bh_s, Bl_s, krow * BS_STRIDE + 2 * p, v.x, v.y);
            }
        }
        __syncthreads();

        #pragma unroll
        for (int ks = 0; ks < 4; ks++) {
            int kk = ks * 16;
            uint32_t Ahf[2][4], Alf[2][4], Bhf[2][4], Blf[2][4];
            #pragma unroll
            for (int mf = 0; mf < 2; mf++) {
                uint32_t ao = (uint32_t)(((a_row + mf * 16) * AS_STRIDE + kk + a_ko) * 2);
                ldsm_x4(Ahf[mf], uAh + ao);
                ldsm_x4(Alf[mf], uAl + ao);
            }
            #pragma unroll
            for (int half = 0; half < 2; half++) {
                uint32_t bo = (uint32_t)(((kk + b_kr) * BS_STRIDE + b_nc + half * 16) * 2);
                ldsm_x4_t(Bhf[half], uBh + bo);
                ldsm_x4_t(Blf[half], uBl + bo);
            }
            // term-major: 8 independent accumulators per sweep
            #pragma unroll
            for (int mf = 0; mf < 2; mf++)
                #pragma unroll
                for (int nf = 0; nf < 4; nf++)
                    mma16816(acc[mf][nf], Ahf[mf], &Bhf[nf >> 1][(nf & 1) * 2]);
            #pragma unroll
            for (int mf = 0; mf < 2; mf++)
                #pragma unroll
                for (int nf = 0; nf < 4; nf++)
                    mma16816(acc[mf][nf], Ahf[mf], &Blf[nf >> 1][(nf & 1) * 2]);
            #pragma unroll
            for (int mf = 0; mf < 2; mf++)
                #pragma unroll
                for (int nf = 0; nf < 4; nf++)
                    mma16816(acc[mf][nf], Alf[mf], &Bhf[nf >> 1][(nf & 1) * 2]);
        }
    }

    float* outbuf = (sel == 0) ? g_q : (sel == 1) ? g_k : g_v;
    const float* Agp = (sel == 0) ? g_Aq : g_Ak;
    const float* Bgp = (sel == 0) ? g_Bq : g_Bk;
    const float* yub = g_yu + b * HW;

    int gid = lane >> 2, tig = lane & 3;
    #pragma unroll
    for (int mf = 0; mf < 2; mf++) {
        #pragma unroll
        for (int rh = 0; rh < 2; rh++) {
            int c = mrow0 + wm * 32 + mf * 16 + gid + rh * 8;
            float bi = bias[c];
            float Ag = 0.f, Bg = 0.f;
            if (sel < 2) { Ag = Agp[c]; Bg = Bgp[c]; }
            #pragma unroll
            for (int nf = 0; nf < 4; nf++) {
                int ng = n0 + wn * 32 + nf * 8 + 2 * tig;
                float v0 = acc[mf][nf][rh * 2 + 0] + bi;
                float v1 = acc[mf][nf][rh * 2 + 1] + bi;
                if (sel < 2) {
                    v0 *= (yub[ng]     * Ag + Bg);
                    v1 *= (yub[ng + 1] * Ag + Bg);
                }
                int h = ng / 96;
                int w = ng - h * 96;
                *reinterpret_cast<float2*>(
                    &outbuf[(((size_t)b * H_SZ + h) * C_SZ + c) * W_SZ + w]) =
                    make_float2(v0, v1);
            }
        }
    }
}

// ---------------- kernel 3: channel attention, mma.sync 3-term, term-major order ----------------
#define oQh 0
#define oQl 13312
#define oKh 26624
#define oKl 53248
#define oPh 0
#define oPl 33792
#define oVh 67584
#define oVl 80896
#define RED_OFF 188416
#define ATT_SMEM_BYTES 190464

__global__ __launch_bounds__(512, 1) void attn_kernel(float* __restrict__ out)
{
    extern __shared__ __align__(16) char dynsm[];
    __nv_bfloat16* sb = (__nv_bfloat16*)dynsm;
    float* red_max = (float*)(dynsm + RED_OFF);
    float* red_sum = red_max + 256;
    uint32_t u0 = smem_u32(dynsm);

    int bid = blockIdx.x;              // 0..1535
    int bh  = bid >> 1;
    int t   = bid & 1;
    int b   = bh / H_SZ;
    int h   = bh - b * H_SZ;
    const float* Q = g_q + (size_t)bh * C_SZ * W_SZ + (size_t)t * 128 * W_SZ;
    const float* K = g_k + (size_t)bh * C_SZ * W_SZ;
    const float* V = g_v + (size_t)bh * C_SZ * W_SZ;

    int tid  = threadIdx.x;
    int lane = tid & 31;
    int wid  = tid >> 5;
    int wm2  = wid >> 1;      // 0..7  (16 rows each)
    int wn2  = wid & 1;       // 0..1
    int gid  = lane >> 2;
    int tig  = lane & 3;

    int arow = (lane & 7) + ((lane >> 3) & 1) * 8;
    int ako  = ((lane >> 4) & 1) * 8;
    int bno  = (lane & 7) + ((lane >> 4) & 1) * 8;
    int bko  = ((lane >> 3) & 1) * 8;
    int vkr  = (lane & 7) + ((lane >> 3) & 1) * 8;
    int vno  = ((lane >> 4) & 1) * 8;

    // ---- stage Q [128][96] and K [256][96] hi/lo ----
    #pragma unroll
    for (int u = 0; u < 12; u++) {
        int f2i = tid + u * 512;
        int r = f2i / 48, p = f2i - r * 48;
        float2 v = *reinterpret_cast<const float2*>(&Q[r * 96 + 2 * p]);
        split_store2(sb + oQh, sb + oQl, r * 104 + 2 * p, v.x, v.y);
    }
    #pragma unroll
    for (int u = 0; u < 24; u++) {
        int f2i = tid + u * 512;
        int r = f2i / 48, p = f2i - r * 48;
        float2 v = *reinterpret_cast<const float2*>(&K[r * 96 + 2 * p]);
        split_store2(sb + oKh, sb + oKl, r * 104 + 2 * p, v.x, v.y);
    }
    __syncthreads();

    // ---- S = Q @ K^T, B n-frags in pairs -> 4 independent accs per term sweep ----
    float acc[16][4];
    #pragma unroll
    for (int nf = 0; nf < 16; nf++)
        #pragma unroll
        for (int r = 0; r < 4; r++) acc[nf][r] = 0.f;

    #pragma unroll 1
    for (int ks = 0; ks < 6; ks++) {
        uint32_t Ah[4], Al[4];
        uint32_t aoff = (uint32_t)(((wm2 * 16 + arow) * 104 + ks * 16 + ako) * 2);
        ldsm_x4(Ah, u0 + oQh * 2 + aoff);
        ldsm_x4(Al, u0 + oQl * 2 + aoff);
        #pragma unroll
        for (int np = 0; np < 4; np++) {   // pairs of n-frags
            uint32_t Bh[2][4], Bl[2][4];
            #pragma unroll
            for (int p = 0; p < 2; p++) {
                int n = wn2 * 128 + (np * 2 + p) * 16 + bno;
                uint32_t boff = (uint32_t)((n * 104 + ks * 16 + bko) * 2);
                ldsm_x4(Bh[p], u0 + oKh * 2 + boff);
                ldsm_x4(Bl[p], u0 + oKl * 2 + boff);
            }
            // term-major over 4 independent accs
            #pragma unroll
            for (int p = 0; p < 2; p++)
                #pragma unroll
                for (int sub = 0; sub < 2; sub++)
                    mma16816(acc[(np * 2 + p) * 2 + sub], Ah, &Bh[p][sub * 2]);
            #pragma unroll
            for (int p = 0; p < 2; p++)
                #pragma unroll
                for (int sub = 0; sub < 2; sub++)
                    mma16816(acc[(np * 2 + p) * 2 + sub], Ah, &Bl[p][sub * 2]);
            #pragma unroll
            for (int p = 0; p < 2; p++)
                #pragma unroll
                for (int sub = 0; sub < 2; sub++)
                    mma16816(acc[(np * 2 + p) * 2 + sub], Al, &Bh[p][sub * 2]);
        }
    }

    // ---- softmax ----
    const float inv_s = 0.17677669529663687f;  // 1/sqrt(32)
    float gm[2], rs_[2];

    #pragma unroll
    for (int rh = 0; rh < 2; rh++) {
        float m = -1e30f;
        #pragma unroll
        for (int nf = 0; nf < 16; nf++)
            m = fmaxf(m, fmaxf(acc[nf][rh * 2], acc[nf][rh * 2 + 1]));
        m = fmaxf(m, __shfl_xor_sync(0xffffffffu, m, 1));
        m = fmaxf(m, __shfl_xor_sync(0xffffffffu, m, 2));
        if (tig == 0) red_max[(wm2 * 16 + gid + rh * 8) * 2 + wn2] = m;
    }
    __syncthreads();
    #pragma unroll
    for (int rh = 0; rh < 2; rh++) {
        int r = wm2 * 16 + gid + rh * 8;
        gm[rh] = fmaxf(red_max[r * 2], red_max[r * 2 + 1]);
    }
    #pragma unroll
    for (int rh = 0; rh < 2; rh++) {
        float s = 0.f;
        #pragma unroll
        for (int nf = 0; nf < 16; nf++) {
            float e0 = __expf((acc[nf][rh * 2]     - gm[rh]) * inv_s);
            float e1 = __expf((acc[nf][rh * 2 + 1] - gm[rh]) * inv_s);
            acc[nf][rh * 2] = e0;  acc[nf][rh * 2 + 1] = e1;
            s += e0 + e1;
        }
        s += __shfl_xor_sync(0xffffffffu, s, 1);
        s += __shfl_xor_sync(0xffffffffu, s, 2);
        if (tig == 0) red_sum[(wm2 * 16 + gid + rh * 8) * 2 + wn2] = s;
    }
    __syncthreads();
    #pragma unroll
    for (int rh = 0; rh < 2; rh++) {
        int r = wm2 * 16 + gid + rh * 8;
        rs_[rh] = 1.f / (red_sum[r * 2] + red_sum[r * 2 + 1]);
    }

    // ---- store P hi/lo [m][k=256] stride 264; stage V chunk 0 ----
    #pragma unroll
    for (int rh = 0; rh < 2; rh++) {
        int r = wm2 * 16 + gid + rh * 8;
        float rr = rs_[rh];
        #pragma unroll
        for (int nf = 0; nf < 16; nf++) {
            int col = wn2 * 128 + nf * 8 + 2 * tig;
            split_store2(sb + oPh, sb + oPl, r * 264 + col,
                         acc[nf][rh * 2] * rr, acc[nf][rh * 2 + 1] * rr);
        }
    }
    #pragma unroll
    for (int u = 0; u < 12; u++) {
        int f2i = tid + u * 512;
        int r = f2i / 48, p = f2i - r * 48;
        float2 v = *reinterpret_cast<const float2*>(&V[r * 96 + 2 * p]);
        split_store2(sb + oVh, sb + oVl, r * 104 + 2 * p, v.x, v.y);
    }
    __syncthreads();

    // ---- O = P @ V, all 3 V n-frags resident -> 6 independent accs per term sweep ----
    float ao[6][4];
    #pragma unroll
    for (int nf = 0; nf < 6; nf++)
        #pragma unroll
        for (int r = 0; r < 4; r++) ao[nf][r] = 0.f;

    #pragma unroll 1
    for (int c = 0; c < 2; c++) {
        if (c == 1) {
            __syncthreads();
            #pragma unroll
            for (int u = 0; u < 12; u++) {
                int f2i = tid + u * 512;
                int r = f2i / 48, p = f2i - r * 48;
                float2 v = *reinterpret_cast<const float2*>(&V[(128 + r) * 96 + 2 * p]);
                split_store2(sb + oVh, sb + oVl, r * 104 + 2 * p, v.x, v.y);
            }
            __syncthreads();
        }
        #pragma unroll
        for (int ks = 0; ks < 8; ks++) {
            uint32_t Ph[4], Pl[4];
            uint32_t poff = (uint32_t)(((wm2 * 16 + arow) * 264 + c * 128 + ks * 16 + ako) * 2);
            ldsm_x4(Ph, u0 + oPh * 2 + poff);
            ldsm_x4(Pl, u0 + oPl * 2 + poff);
            uint32_t Vh[3][4], Vl[3][4];
            #pragma unroll
            for (int nfp = 0; nfp < 3; nfp++) {
                int krow = ks * 16 + vkr;
                int n = wn2 * 48 + nfp * 16 + vno;
                uint32_t voff = (uint32_t)((krow * 104 + n) * 2);
                ldsm_x4_t(Vh[nfp], u0 + oVh * 2 + voff);
                ldsm_x4_t(Vl[nfp], u0 + oVl * 2 + voff);
            }
            #pragma unroll
            for (int nfp = 0; nfp < 3; nfp++)
                #pragma unroll
                for (int sub = 0; sub < 2; sub++)
                    mma16816(ao[nfp * 2 + sub], Ph, &Vh[nfp][sub * 2]);
            #pragma unroll
            for (int nfp = 0; nfp < 3; nfp++)
                #pragma unroll
                for (int sub = 0; sub < 2; sub++)
                    mma16816(ao[nfp * 2 + sub], Ph, &Vl[nfp][sub * 2]);
            #pragma unroll
            for (int nfp = 0; nfp < 3; nfp++)
                #pragma unroll
                for (int sub = 0; sub < 2; sub++)
                    mma16816(ao[nfp * 2 + sub], Pl, &Vh[nfp][sub * 2]);
        }
    }

    // ---- write O ----
    #pragma unroll
    for (int rh = 0; rh < 2; rh++) {
        int r = wm2 * 16 + gid + rh * 8;
        int ch = t * 128 + r;
        float* ob = out + ((size_t)b * C_SZ + ch) * HW + (size_t)h * W_SZ;
        #pragma unroll
        for (int nf = 0; nf < 6; nf++) {
            int col = wn2 * 48 + nf * 8 + 2 * tig;
            *reinterpret_cast<float2*>(&ob[col]) =
                make_float2(ao[nf][rh * 2], ao[nf][rh * 2 + 1]);
        }
    }
}

// ---------------- launch ----------------
extern "C" void kernel_launch(void* const* d_in, const int* in_sizes, int n_in,
                              void* d_out, int out_size)
{
    const float* x  = (const float*)d_in[0];
    const float* y  = (const float*)d_in[1];
    const float* wy = (const float*)d_in[2];
    const float* by = (const float*)d_in[3];
    const float* wq = (const float*)d_in[4];
    const float* bq = (const float*)d_in[5];
    const float* wk = (const float*)d_in[6];
    const float* bk = (const float*)d_in[7];
    const float* wv = (const float*)d_in[8];
    const float* bv = (const float*)d_in[9];
    float* out = (float*)d_out;

    cudaFuncSetAttribute(attn_kernel, cudaFuncAttributeMaxDynamicSharedMemorySize,
                         ATT_SMEM_BYTES);
    cudaFuncSetAttribute(conv_tensor_kernel, cudaFuncAttributeMaxDynamicSharedMemorySize,
                         CV_SMEM_BYTES);

    prep_kernel<<<1, 256>>>(wy, by, wq, bq, wk, bk);
    upsample_kernel<<<(B_SZ * HW + 255) / 256, 256>>>(y);
    dim3 g(HW / 128, 768 / 128, B_SZ);   // (72, 6, 8)
    conv_tensor_kernel<<<g, 512, CV_SMEM_BYTES>>>(x, wq, bq, wk, bk, wv, bv);
    attn_kernel<<<2 * B_SZ * H_SZ, 512, ATT_SMEM_BYTES>>>(out);
}